// round 2
// baseline (speedup 1.0000x reference)
#include <cuda_runtime.h>
#include <math.h>

#define BB   2
#define NSEQ 2048
#define DMOD 1024
#define NH   16
#define HDIM 64
#define NC   4

// ---------------- scratch (device globals; no allocation allowed) ----------------
__device__ float g_q[(size_t)BB * NH * NSEQ * HDIM];     // 16 MB
__device__ float g_k[(size_t)BB * NH * NSEQ * HDIM];     // 16 MB
__device__ float g_v[(size_t)BB * NH * NSEQ * HDIM];     // 16 MB
__device__ float g_att[(size_t)BB * NSEQ * DMOD];        // 16 MB
__device__ float g_bias[(size_t)BB * NSEQ * NSEQ];       // 33.5 MB

// ---------------- SGEMM: C[M,Nt] = A[M,K] @ W[Nt,K]^T ----------------
// 128x128 tile, BK=8, 256 threads, 8x8 per-thread with split 4+4 layout.
// MODE 0: plain row-major store to Cout.
// MODE 1: QKV scatter into g_q/g_k/g_v head-major (B,H,N,HD).
template <int MODE>
__global__ void __launch_bounds__(256)
sgemm_kernel(const float* __restrict__ A, const float* __restrict__ W,
             float* __restrict__ Cout, int M, int Nt, int K)
{
    __shared__ float As[8][128];
    __shared__ float Bs[8][128];

    const int tid = threadIdx.x;
    const int tx  = tid & 15;
    const int ry  = tid >> 4;
    const int m0  = blockIdx.y * 128;
    const int n0  = blockIdx.x * 128;
    const int la_m = tid >> 1;
    const int la_k = (tid & 1) * 4;

    float acc[8][8];
#pragma unroll
    for (int i = 0; i < 8; i++)
#pragma unroll
        for (int j = 0; j < 8; j++) acc[i][j] = 0.f;

    const float* Ap = A + (size_t)(m0 + la_m) * K + la_k;
    const float* Wp = W + (size_t)(n0 + la_m) * K + la_k;

    for (int k0 = 0; k0 < K; k0 += 8) {
        float4 av = *(const float4*)(Ap + k0);
        float4 wv = *(const float4*)(Wp + k0);
        __syncthreads();
        As[la_k + 0][la_m] = av.x;
        As[la_k + 1][la_m] = av.y;
        As[la_k + 2][la_m] = av.z;
        As[la_k + 3][la_m] = av.w;
        Bs[la_k + 0][la_m] = wv.x;
        Bs[la_k + 1][la_m] = wv.y;
        Bs[la_k + 2][la_m] = wv.z;
        Bs[la_k + 3][la_m] = wv.w;
        __syncthreads();
#pragma unroll
        for (int kk = 0; kk < 8; kk++) {
            float a[8], b[8];
            *(float4*)&a[0] = *(const float4*)&As[kk][4 * ry];
            *(float4*)&a[4] = *(const float4*)&As[kk][64 + 4 * ry];
            *(float4*)&b[0] = *(const float4*)&Bs[kk][4 * tx];
            *(float4*)&b[4] = *(const float4*)&Bs[kk][64 + 4 * tx];
#pragma unroll
            for (int i = 0; i < 8; i++)
#pragma unroll
                for (int j = 0; j < 8; j++)
                    acc[i][j] = fmaf(a[i], b[j], acc[i][j]);
        }
    }

#pragma unroll
    for (int i = 0; i < 8; i++) {
        int m = m0 + ((i < 4) ? (4 * ry + i) : (64 + 4 * ry + (i - 4)));
#pragma unroll
        for (int g = 0; g < 2; g++) {
            int j0 = n0 + g * 64 + 4 * tx;
            float4 val = make_float4(acc[i][4 * g + 0], acc[i][4 * g + 1],
                                     acc[i][4 * g + 2], acc[i][4 * g + 3]);
            if (MODE == 0) {
                *(float4*)&Cout[(size_t)m * Nt + j0] = val;
            } else {
                int which = j0 / DMOD;         // 0:q 1:k 2:v
                int rem   = j0 % DMOD;
                int h     = rem / HDIM;
                int dd    = rem % HDIM;        // 4tx<=60 -> 4 elems stay in-head
                int bb    = m / NSEQ;
                int nn    = m % NSEQ;
                float* dst = (which == 0) ? g_q : (which == 1) ? g_k : g_v;
                *(float4*)&dst[((size_t)(bb * NH + h) * NSEQ + nn) * HDIM + dd] = val;
            }
        }
    }
}

// ---------------- RMSNorm on q and k: one warp per (b,h,n) row of 64 ----------------
__global__ void __launch_bounds__(256)
rmsnorm_kernel(const float* __restrict__ qw, const float* __restrict__ kw)
{
    int gw   = (blockIdx.x * 256 + threadIdx.x) >> 5;
    int lane = threadIdx.x & 31;
    const int ROWS = BB * NH * NSEQ;
    float* base;
    const float* w;
    int row;
    if (gw < ROWS) { base = g_q; w = qw; row = gw; }
    else           { base = g_k; w = kw; row = gw - ROWS; }
    float* p = base + (size_t)row * HDIM;
    float v0 = p[lane], v1 = p[lane + 32];
    float s = v0 * v0 + v1 * v1;
#pragma unroll
    for (int o = 16; o > 0; o >>= 1) s += __shfl_xor_sync(0xffffffffu, s, o);
    float r = rsqrtf(s * (1.0f / HDIM) + 1e-6f);
    p[lane]      = v0 * r * w[lane];
    p[lane + 32] = v1 * r * w[lane + 32];
}

// ---------------- bias precompute: one block per (b,q) row ----------------
// same[b,q,k] = sum_c cm[b,c,q]*cm[b,c,k]; rowmax-normalized; + 0.3*interaction
__global__ void __launch_bounds__(256)
bias_kernel(const float* __restrict__ cm, const float* __restrict__ im)
{
    int bq = blockIdx.x;
    int b = bq / NSEQ, q = bq % NSEQ;
    const float* cmb = cm + (size_t)b * NC * NSEQ;
    float c0 = cmb[q], c1 = cmb[NSEQ + q], c2 = cmb[2 * NSEQ + q], c3 = cmb[3 * NSEQ + q];

    float mx = 0.f;
    for (int k = threadIdx.x; k < NSEQ; k += 256) {
        float s = c0 * cmb[k] + c1 * cmb[NSEQ + k] + c2 * cmb[2 * NSEQ + k] + c3 * cmb[3 * NSEQ + k];
        mx = fmaxf(mx, s);
    }
    __shared__ float red[8];
#pragma unroll
    for (int o = 16; o > 0; o >>= 1) mx = fmaxf(mx, __shfl_xor_sync(0xffffffffu, mx, o));
    if ((threadIdx.x & 31) == 0) red[threadIdx.x >> 5] = mx;
    __syncthreads();
    if (threadIdx.x == 0) {
        float m = red[0];
#pragma unroll
        for (int wN = 1; wN < 8; wN++) m = fmaxf(m, red[wN]);
        red[0] = fmaxf(m, 1e-6f);      // jnp.clip(max, 1e-6)
    }
    __syncthreads();
    float inv = 1.f / red[0];
    const float* imr = im + (size_t)bq * NSEQ;
    float* br = g_bias + (size_t)bq * NSEQ;
    for (int k = threadIdx.x; k < NSEQ; k += 256) {
        float s = c0 * cmb[k] + c1 * cmb[NSEQ + k] + c2 * cmb[2 * NSEQ + k] + c3 * cmb[3 * NSEQ + k];
        br[k] = 2.f * s * inv - 1.f + 0.3f * imr[k];   // (same-0.5)*2 + boost*im
    }
}

// ---------------- fused flash attention ----------------
// grid (N/64, B*H); 256 threads as 16(tx=k/d cols) x 16(ty=q rows); 4x4 frags.
// Qs natural [64][65]; Kt d-major [64][64] with XOR group swizzle (conflict-free
// float4 b-frag reads); Vs natural [64][64]; Ps natural [64][65].
#define ATTN_SMEM ((64 * 65 + 64 * 64 + 64 * 64 + 64 * 65) * 4)

__global__ void __launch_bounds__(256)
attn_kernel(const float* __restrict__ gate)
{
    extern __shared__ float smem[];
    float* Qs = smem;                   // 64 x 65
    float* Kt = Qs + 64 * 65;           // 64 x 64 (d-major, swizzled)
    float* Vs = Kt + 64 * 64;           // 64 x 64 (k-major)
    float* Ps = Vs + 64 * 64;           // 64 x 65

    const int tid = threadIdx.x;
    const int tx = tid & 15, ty = tid >> 4;
    const int bh = blockIdx.y;
    const int b = bh >> 4, h = bh & 15;
    const int q0 = blockIdx.x * 64;
    const float g3 = 3.f * fminf(fmaxf(gate[h], 0.f), 1.f);

    const float* Qg = g_q + ((size_t)bh * NSEQ + q0) * HDIM;
    const float* Kg = g_k + (size_t)bh * NSEQ * HDIM;
    const float* Vg = g_v + (size_t)bh * NSEQ * HDIM;
    const float* biasRow = g_bias + ((size_t)b * NSEQ + q0) * NSEQ;

    // load Q tile once (natural layout, padded rows)
    for (int i = tid; i < 64 * 16; i += 256) {
        int r = i >> 4, d4 = (i & 15) << 2;
        float4 v = *(const float4*)(Qg + (size_t)r * HDIM + d4);
        float* qp = Qs + r * 65 + d4;
        qp[0] = v.x; qp[1] = v.y; qp[2] = v.z; qp[3] = v.w;
    }

    float m_i[4], l_i[4], o[4][4];
#pragma unroll
    for (int i = 0; i < 4; i++) {
        m_i[i] = -1e30f; l_i[i] = 0.f;
#pragma unroll
        for (int j = 0; j < 4; j++) o[i][j] = 0.f;
    }

    for (int kt = 0; kt < NSEQ / 64; kt++) {
        __syncthreads();   // prior P@V done before overwriting Kt/Vs
        for (int i = tid; i < 64 * 16; i += 256) {
            int r = i >> 4, d4 = (i & 15) << 2;
            size_t off = ((size_t)(kt * 64 + r)) * HDIM + d4;
            float4 kv = *(const float4*)(Kg + off);
            float4 vv = *(const float4*)(Vg + off);
            int gI = r >> 2, ro = r & 3;
            float kvv[4] = {kv.x, kv.y, kv.z, kv.w};
#pragma unroll
            for (int u = 0; u < 4; u++) {
                int d  = d4 + u;
                int sg = gI ^ ((d >> 2) & 15);
                Kt[d * 64 + sg * 4 + ro] = kvv[u];
            }
            *(float4*)(Vs + r * 64 + d4) = vv;
        }
        __syncthreads();

        // S = Q K^T (4x4 per thread)
        float s[4][4];
#pragma unroll
        for (int i = 0; i < 4; i++)
#pragma unroll
            for (int j = 0; j < 4; j++) s[i][j] = 0.f;

#pragma unroll 8
        for (int d = 0; d < 64; d++) {
            float a4[4];
#pragma unroll
            for (int i = 0; i < 4; i++) a4[i] = Qs[(4 * ty + i) * 65 + d]; // broadcast
            int sg = tx ^ ((d >> 2) & 15);
            float4 bv = *(const float4*)(Kt + d * 64 + sg * 4);            // conflict-free
            float b4[4] = {bv.x, bv.y, bv.z, bv.w};
#pragma unroll
            for (int i = 0; i < 4; i++)
#pragma unroll
                for (int j = 0; j < 4; j++) s[i][j] = fmaf(a4[i], b4[j], s[i][j]);
        }

        // scale + gated bias + online softmax
#pragma unroll
        for (int i = 0; i < 4; i++) {
            float4 bb = *(const float4*)(biasRow + (size_t)(4 * ty + i) * NSEQ + kt * 64 + 4 * tx);
            float b4[4] = {bb.x, bb.y, bb.z, bb.w};
            float rm = -1e30f;
#pragma unroll
            for (int j = 0; j < 4; j++) {
                s[i][j] = fmaf(s[i][j], 0.125f, g3 * b4[j]);
                rm = fmaxf(rm, s[i][j]);
            }
#pragma unroll
            for (int off = 1; off < 16; off <<= 1)
                rm = fmaxf(rm, __shfl_xor_sync(0xffffffffu, rm, off));
            float mn = fmaxf(m_i[i], rm);
            float alpha = __expf(m_i[i] - mn);
            m_i[i] = mn;
            float rs = 0.f;
#pragma unroll
            for (int j = 0; j < 4; j++) { s[i][j] = __expf(s[i][j] - mn); rs += s[i][j]; }
#pragma unroll
            for (int off = 1; off < 16; off <<= 1)
                rs += __shfl_xor_sync(0xffffffffu, rs, off);
            l_i[i] = l_i[i] * alpha + rs;
#pragma unroll
            for (int j = 0; j < 4; j++) o[i][j] *= alpha;
        }

        // stage P and accumulate O += P @ V
#pragma unroll
        for (int i = 0; i < 4; i++)
#pragma unroll
            for (int j = 0; j < 4; j++) Ps[(4 * ty + i) * 65 + 4 * tx + j] = s[i][j];
        __syncthreads();

#pragma unroll 8
        for (int kk = 0; kk < 64; kk++) {
            float a4[4];
#pragma unroll
            for (int i = 0; i < 4; i++) a4[i] = Ps[(4 * ty + i) * 65 + kk]; // broadcast
            float4 bv = *(const float4*)(Vs + kk * 64 + 4 * tx);
            float b4[4] = {bv.x, bv.y, bv.z, bv.w};
#pragma unroll
            for (int i = 0; i < 4; i++)
#pragma unroll
                for (int j = 0; j < 4; j++) o[i][j] = fmaf(a4[i], b4[j], o[i][j]);
        }
    }

    // epilogue: normalize and write (B,N,D) layout
    float* op = g_att + ((size_t)b * NSEQ + q0) * DMOD + h * HDIM;
#pragma unroll
    for (int i = 0; i < 4; i++) {
        float inv = 1.f / l_i[i];
        float4 w = make_float4(o[i][0] * inv, o[i][1] * inv, o[i][2] * inv, o[i][3] * inv);
        *(float4*)(op + (size_t)(4 * ty + i) * DMOD + 4 * tx) = w;
    }
}

// ---------------- launch ----------------
extern "C" void kernel_launch(void* const* d_in, const int* in_sizes, int n_in,
                              void* d_out, int out_size)
{
    (void)in_sizes; (void)n_in; (void)out_size;
    const float* x    = (const float*)d_in[0];
    const float* cm   = (const float*)d_in[1];
    const float* im   = (const float*)d_in[2];
    const float* wqkv = (const float*)d_in[3];
    const float* wout = (const float*)d_in[4];
    const float* qnw  = (const float*)d_in[5];
    const float* knw  = (const float*)d_in[6];
    const float* gate = (const float*)d_in[7];
    float* out = (float*)d_out;

    void* attp = nullptr;
    cudaGetSymbolAddress(&attp, g_att);
    cudaFuncSetAttribute(attn_kernel, cudaFuncAttributeMaxDynamicSharedMemorySize, ATTN_SMEM);

    const int M = BB * NSEQ;   // 4096

    // 1) QKV projection with head-scatter epilogue
    sgemm_kernel<1><<<dim3((3 * DMOD) / 128, M / 128), 256>>>(x, wqkv, nullptr, M, 3 * DMOD, DMOD);
    // 2) RMSNorm q and k (one warp per 64-elem row)
    rmsnorm_kernel<<<(2 * BB * NH * NSEQ * 32) / 256, 256>>>(qnw, knw);
    // 3) bias precompute (shared by all heads)
    bias_kernel<<<BB * NSEQ, 256>>>(cm, im);
    // 4) fused attention
    attn_kernel<<<dim3(NSEQ / 64, BB * NH), 256, ATTN_SMEM>>>(gate);
    // 5) output projection straight into d_out
    sgemm_kernel<0><<<dim3(DMOD / 128, M / 128), 256>>>((const float*)attp, wout, out, M, DMOD, DMOD);
}

// round 4
// speedup vs baseline: 1.4825x; 1.4825x over previous
#include <cuda_runtime.h>
#include <cuda_bf16.h>
#include <math.h>
#include <stdint.h>

#define BB   2
#define NSEQ 2048
#define DMOD 1024
#define NH   16
#define HDIM 64
#define NC   4

// ---------------- scratch (device globals; no allocation allowed) ----------------
__device__ float g_q[(size_t)BB * NH * NSEQ * HDIM];
__device__ float g_k[(size_t)BB * NH * NSEQ * HDIM];
__device__ float g_v[(size_t)BB * NH * NSEQ * HDIM];
__device__ float g_att[(size_t)BB * NSEQ * DMOD];
__device__ float g_bias[(size_t)BB * NSEQ * NSEQ];

// bf16 split operands, stored pre-swizzled in 128x64 SW128 tiles (16KB each)
__device__ __nv_bfloat16 gXh[(size_t)4096 * 1024];
__device__ __nv_bfloat16 gXl[(size_t)4096 * 1024];
__device__ __nv_bfloat16 gWqh[(size_t)3072 * 1024];
__device__ __nv_bfloat16 gWql[(size_t)3072 * 1024];
__device__ __nv_bfloat16 gWoh[(size_t)1024 * 1024];
__device__ __nv_bfloat16 gWol[(size_t)1024 * 1024];
__device__ __nv_bfloat16 gAh2[(size_t)4096 * 1024];
__device__ __nv_bfloat16 gAl2[(size_t)4096 * 1024];

// ---------------- PTX helpers (base sm_103-legal only) ----------------
__device__ __forceinline__ uint32_t smem_u32(const void* p) {
    uint32_t a;
    asm("{ .reg .u64 t; cvta.to.shared.u64 t, %1; cvt.u32.u64 %0, t; }" : "=r"(a) : "l"(p));
    return a;
}

#define CP_ASYNC16(dst, src) \
    asm volatile("cp.async.cg.shared.global [%0], [%1], 16;" :: "r"(dst), "l"(src) : "memory")
#define CP_COMMIT() asm volatile("cp.async.commit_group;" ::: "memory")
#define CP_WAIT0()  asm volatile("cp.async.wait_group 0;" ::: "memory")
#define CP_WAIT1()  asm volatile("cp.async.wait_group 1;" ::: "memory")

#define LDMX4(r, a) \
    asm volatile("ldmatrix.sync.aligned.m8n8.x4.shared.b16 {%0,%1,%2,%3}, [%4];" \
        : "=r"((r)[0]), "=r"((r)[1]), "=r"((r)[2]), "=r"((r)[3]) : "r"(a))

__device__ __forceinline__ void mma_bf16(float* d, uint32_t a0, uint32_t a1,
                                         uint32_t a2, uint32_t a3,
                                         uint32_t b0, uint32_t b1) {
    asm volatile(
        "mma.sync.aligned.m16n8k16.row.col.f32.bf16.bf16.f32 "
        "{%0,%1,%2,%3},{%4,%5,%6,%7},{%8,%9},{%0,%1,%2,%3};"
        : "+f"(d[0]), "+f"(d[1]), "+f"(d[2]), "+f"(d[3])
        : "r"(a0), "r"(a1), "r"(a2), "r"(a3), "r"(b0), "r"(b1));
}

// ---------------- split-conversion: fp32 row-major -> blocked swizzled bf16 hi/lo ----------------
// Tiles of 128 rows x 64 cols (16KB), SW128 swizzle applied, tile index = rowTile*(K/64)+chunk.
__global__ void __launch_bounds__(256)
conv_split_kernel(const float* __restrict__ src, __nv_bfloat16* __restrict__ dh,
                  __nv_bfloat16* __restrict__ dl, int K)
{
    size_t idx = ((size_t)blockIdx.x * 256 + threadIdx.x) * 8;
    int r  = (int)(idx / K);
    int c0 = (int)(idx % K);
    float4 v0 = *(const float4*)(src + idx);
    float4 v1 = *(const float4*)(src + idx + 4);
    float f[8] = {v0.x, v0.y, v0.z, v0.w, v1.x, v1.y, v1.z, v1.w};
    __nv_bfloat16 h[8], l[8];
#pragma unroll
    for (int i = 0; i < 8; i++) {
        h[i] = __float2bfloat16(f[i]);
        l[i] = __float2bfloat16(f[i] - __bfloat162float(h[i]));
    }
    int rt = r >> 7, lr = r & 127, ch = c0 >> 6, lc = c0 & 63;
    size_t tile = (size_t)rt * (K >> 6) + ch;
    uint32_t off = lr * 128 + lc * 2;
    uint32_t sw = off ^ ((off >> 3) & 0x70);
    size_t db = tile * 16384 + sw;
    *(uint4*)((char*)dh + db) = *(uint4*)h;
    *(uint4*)((char*)dl + db) = *(uint4*)l;
}

// ---------------- HMMA GEMM: C[M,Nt] = A[M,K] @ W[Nt,K]^T, 3-term bf16 split ----------------
// grid (Nt/128, M/128), 256 threads (8 warps as 4m x 2n), warp tile 32x64.
// Double-buffered cp.async from pre-swizzled tiles; MODE 0: row-major store, MODE 1: QKV scatter.
#define GEMM_SMEM (2 * 4 * 16384)   // 2 buffers x (Ah,Al,Bh,Bl) x 16KB = 128KB

template <int MODE>
__global__ void __launch_bounds__(256)
gemm_hmma(const char* __restrict__ Ah, const char* __restrict__ Al,
          const char* __restrict__ Bh, const char* __restrict__ Bl,
          float* __restrict__ Cout, int KC /* K/64 */, int Nt)
{
    extern __shared__ char smraw[];
    const uint32_t smemS = smem_u32(smraw);
    const int tid  = threadIdx.x;
    const int lane = tid & 31;
    const int warp = tid >> 5;
    const int wm = warp & 3;      // m tile of 32
    const int wn = warp >> 2;     // n tile of 64

    const size_t tA0 = (size_t)blockIdx.y * KC * 16384;
    const size_t tB0 = (size_t)blockIdx.x * KC * 16384;

    float acc[2][8][4];
#pragma unroll
    for (int i = 0; i < 2; i++)
#pragma unroll
        for (int j = 0; j < 8; j++)
#pragma unroll
            for (int t = 0; t < 4; t++) acc[i][j][t] = 0.f;

    // ldmatrix lane addressing constants (same for every tile)
    const int lrow = lane & 15;                    // row within 16
    const int cb   = (lane >> 4) << 4;             // byte offset of 8-col half

    // prologue: load chunk 0 into buffer 0
    {
        const char* s0 = Ah + tA0 + tid * 16;
        const char* s1 = Al + tA0 + tid * 16;
        const char* s2 = Bh + tB0 + tid * 16;
        const char* s3 = Bl + tB0 + tid * 16;
        uint32_t d0 = smemS + tid * 16;
#pragma unroll
        for (int i = 0; i < 4; i++) {
            CP_ASYNC16(d0 + 0 * 16384 + i * 4096, s0 + i * 4096);
            CP_ASYNC16(d0 + 1 * 16384 + i * 4096, s1 + i * 4096);
            CP_ASYNC16(d0 + 2 * 16384 + i * 4096, s2 + i * 4096);
            CP_ASYNC16(d0 + 3 * 16384 + i * 4096, s3 + i * 4096);
        }
        CP_COMMIT();
    }

    for (int kc = 0; kc < KC; kc++) {
        __syncthreads();   // all warps done computing the buffer we are about to refill
        if (kc + 1 < KC) {
            size_t go = (size_t)(kc + 1) * 16384;
            const char* s0 = Ah + tA0 + go + tid * 16;
            const char* s1 = Al + tA0 + go + tid * 16;
            const char* s2 = Bh + tB0 + go + tid * 16;
            const char* s3 = Bl + tB0 + go + tid * 16;
            uint32_t d0 = smemS + ((kc + 1) & 1) * 65536 + tid * 16;
#pragma unroll
            for (int i = 0; i < 4; i++) {
                CP_ASYNC16(d0 + 0 * 16384 + i * 4096, s0 + i * 4096);
                CP_ASYNC16(d0 + 1 * 16384 + i * 4096, s1 + i * 4096);
                CP_ASYNC16(d0 + 2 * 16384 + i * 4096, s2 + i * 4096);
                CP_ASYNC16(d0 + 3 * 16384 + i * 4096, s3 + i * 4096);
            }
            CP_COMMIT();
            CP_WAIT1();    // current chunk's group complete
        } else {
            CP_WAIT0();
        }
        __syncthreads();

        uint32_t buf = smemS + (kc & 1) * 65536;
        uint32_t aHs = buf, aLs = buf + 16384, bHs = buf + 32768, bLs = buf + 49152;

#pragma unroll
        for (int ks = 0; ks < 4; ks++) {
            const int cbyte = ks * 32 + cb;        // column byte offset within 128B row
            // A fragments (hi and lo) for both 16-row m-frags
            uint32_t ah[2][4], al[2][4];
#pragma unroll
            for (int mf = 0; mf < 2; mf++) {
                int row = wm * 32 + mf * 16 + lrow;
                uint32_t off = row * 128 + cbyte;
                uint32_t sw = off ^ ((row & 7) << 4);
                LDMX4(ah[mf], aHs + sw);
                LDMX4(al[mf], aLs + sw);
            }
            // B fragments: 4 x (16n x 16k) ldmatrix.x4 covering n = 64
#pragma unroll
            for (int nf2 = 0; nf2 < 4; nf2++) {
                int row = wn * 64 + nf2 * 16 + lrow;       // row = n index
                uint32_t off = row * 128 + cbyte;
                uint32_t sw = off ^ ((row & 7) << 4);
                uint32_t bh[4], bl[4];
                LDMX4(bh, bHs + sw);
                LDMX4(bl, bLs + sw);
                // operands: n-lo8 = {r0, r2}, n-hi8 = {r1, r3}
#pragma unroll
                for (int mf = 0; mf < 2; mf++) {
                    float* d0 = acc[mf][2 * nf2];
                    float* d1 = acc[mf][2 * nf2 + 1];
                    mma_bf16(d0, ah[mf][0], ah[mf][1], ah[mf][2], ah[mf][3], bh[0], bh[2]);
                    mma_bf16(d0, ah[mf][0], ah[mf][1], ah[mf][2], ah[mf][3], bl[0], bl[2]);
                    mma_bf16(d0, al[mf][0], al[mf][1], al[mf][2], al[mf][3], bh[0], bh[2]);
                    mma_bf16(d1, ah[mf][0], ah[mf][1], ah[mf][2], ah[mf][3], bh[1], bh[3]);
                    mma_bf16(d1, ah[mf][0], ah[mf][1], ah[mf][2], ah[mf][3], bl[1], bl[3]);
                    mma_bf16(d1, al[mf][0], al[mf][1], al[mf][2], al[mf][3], bh[1], bh[3]);
                }
            }
        }
    }

    // epilogue: registers -> gmem
    const int m0 = blockIdx.y * 128 + wm * 32;
    const int n0 = blockIdx.x * 128 + wn * 64;
#pragma unroll
    for (int mf = 0; mf < 2; mf++) {
#pragma unroll
        for (int nf = 0; nf < 8; nf++) {
            int m = m0 + mf * 16 + (lane >> 2);
            int n = n0 + nf * 8 + (lane & 3) * 2;
            float2 v0 = make_float2(acc[mf][nf][0], acc[mf][nf][1]);  // row m
            float2 v1 = make_float2(acc[mf][nf][2], acc[mf][nf][3]);  // row m+8
            if (MODE == 0) {
                *(float2*)(Cout + (size_t)m * Nt + n)       = v0;
                *(float2*)(Cout + (size_t)(m + 8) * Nt + n) = v1;
            } else {
                int which = n >> 10;
                int rem = n & 1023;
                int h = rem >> 6, dd = rem & 63;
                float* dst = (which == 0) ? g_q : (which == 1) ? g_k : g_v;
                int bb = m >> 11, nn = m & 2047;
                *(float2*)&dst[(((size_t)(bb * NH + h)) * NSEQ + nn) * HDIM + dd] = v0;
                bb = (m + 8) >> 11; nn = (m + 8) & 2047;
                *(float2*)&dst[(((size_t)(bb * NH + h)) * NSEQ + nn) * HDIM + dd] = v1;
            }
        }
    }
}

// ---------------- RMSNorm on q and k: one warp per (b,h,n) row of 64 ----------------
__global__ void __launch_bounds__(256)
rmsnorm_kernel(const float* __restrict__ qw, const float* __restrict__ kw)
{
    int gw   = (blockIdx.x * 256 + threadIdx.x) >> 5;
    int lane = threadIdx.x & 31;
    const int ROWS = BB * NH * NSEQ;
    float* base;
    const float* w;
    int row;
    if (gw < ROWS) { base = g_q; w = qw; row = gw; }
    else           { base = g_k; w = kw; row = gw - ROWS; }
    float* p = base + (size_t)row * HDIM;
    float v0 = p[lane], v1 = p[lane + 32];
    float s = v0 * v0 + v1 * v1;
#pragma unroll
    for (int o = 16; o > 0; o >>= 1) s += __shfl_xor_sync(0xffffffffu, s, o);
    float r = rsqrtf(s * (1.0f / HDIM) + 1e-6f);
    p[lane]      = v0 * r * w[lane];
    p[lane + 32] = v1 * r * w[lane + 32];
}

// ---------------- bias precompute: one block per (b,q) row ----------------
__global__ void __launch_bounds__(256)
bias_kernel(const float* __restrict__ cm, const float* __restrict__ im)
{
    int bq = blockIdx.x;
    int b = bq / NSEQ, q = bq % NSEQ;
    const float* cmb = cm + (size_t)b * NC * NSEQ;
    float c0 = cmb[q], c1 = cmb[NSEQ + q], c2 = cmb[2 * NSEQ + q], c3 = cmb[3 * NSEQ + q];

    float mx = 0.f;
    for (int k = threadIdx.x; k < NSEQ; k += 256) {
        float s = c0 * cmb[k] + c1 * cmb[NSEQ + k] + c2 * cmb[2 * NSEQ + k] + c3 * cmb[3 * NSEQ + k];
        mx = fmaxf(mx, s);
    }
    __shared__ float red[8];
#pragma unroll
    for (int o = 16; o > 0; o >>= 1) mx = fmaxf(mx, __shfl_xor_sync(0xffffffffu, mx, o));
    if ((threadIdx.x & 31) == 0) red[threadIdx.x >> 5] = mx;
    __syncthreads();
    if (threadIdx.x == 0) {
        float m = red[0];
#pragma unroll
        for (int wN = 1; wN < 8; wN++) m = fmaxf(m, red[wN]);
        red[0] = fmaxf(m, 1e-6f);
    }
    __syncthreads();
    float inv = 1.f / red[0];
    const float* imr = im + (size_t)bq * NSEQ;
    float* br = g_bias + (size_t)bq * NSEQ;
    for (int k = threadIdx.x; k < NSEQ; k += 256) {
        float s = c0 * cmb[k] + c1 * cmb[NSEQ + k] + c2 * cmb[2 * NSEQ + k] + c3 * cmb[3 * NSEQ + k];
        br[k] = 2.f * s * inv - 1.f + 0.3f * imr[k];
    }
}

// ---------------- fused flash attention (fp32, unchanged) ----------------
#define ATTN_SMEM ((64 * 65 + 64 * 64 + 64 * 64 + 64 * 65) * 4)

__global__ void __launch_bounds__(256)
attn_kernel(const float* __restrict__ gate)
{
    extern __shared__ float smem[];
    float* Qs = smem;
    float* Kt = Qs + 64 * 65;
    float* Vs = Kt + 64 * 64;
    float* Ps = Vs + 64 * 64;

    const int tid = threadIdx.x;
    const int tx = tid & 15, ty = tid >> 4;
    const int bh = blockIdx.y;
    const int b = bh >> 4, h = bh & 15;
    const int q0 = blockIdx.x * 64;
    const float g3 = 3.f * fminf(fmaxf(gate[h], 0.f), 1.f);

    const float* Qg = g_q + ((size_t)bh * NSEQ + q0) * HDIM;
    const float* Kg = g_k + (size_t)bh * NSEQ * HDIM;
    const float* Vg = g_v + (size_t)bh * NSEQ * HDIM;
    const float* biasRow = g_bias + ((size_t)b * NSEQ + q0) * NSEQ;

    for (int i = tid; i < 64 * 16; i += 256) {
        int r = i >> 4, d4 = (i & 15) << 2;
        float4 v = *(const float4*)(Qg + (size_t)r * HDIM + d4);
        float* qp = Qs + r * 65 + d4;
        qp[0] = v.x; qp[1] = v.y; qp[2] = v.z; qp[3] = v.w;
    }

    float m_i[4], l_i[4], o[4][4];
#pragma unroll
    for (int i = 0; i < 4; i++) {
        m_i[i] = -1e30f; l_i[i] = 0.f;
#pragma unroll
        for (int j = 0; j < 4; j++) o[i][j] = 0.f;
    }

    for (int kt = 0; kt < NSEQ / 64; kt++) {
        __syncthreads();
        for (int i = tid; i < 64 * 16; i += 256) {
            int r = i >> 4, d4 = (i & 15) << 2;
            size_t off = ((size_t)(kt * 64 + r)) * HDIM + d4;
            float4 kv = *(const float4*)(Kg + off);
            float4 vv = *(const float4*)(Vg + off);
            int gI = r >> 2, ro = r & 3;
            float kvv[4] = {kv.x, kv.y, kv.z, kv.w};
#pragma unroll
            for (int u = 0; u < 4; u++) {
                int d  = d4 + u;
                int sg = gI ^ ((d >> 2) & 15);
                Kt[d * 64 + sg * 4 + ro] = kvv[u];
            }
            *(float4*)(Vs + r * 64 + d4) = vv;
        }
        __syncthreads();

        float s[4][4];
#pragma unroll
        for (int i = 0; i < 4; i++)
#pragma unroll
            for (int j = 0; j < 4; j++) s[i][j] = 0.f;

#pragma unroll 8
        for (int d = 0; d < 64; d++) {
            float a4[4];
#pragma unroll
            for (int i = 0; i < 4; i++) a4[i] = Qs[(4 * ty + i) * 65 + d];
            int sg = tx ^ ((d >> 2) & 15);
            float4 bv = *(const float4*)(Kt + d * 64 + sg * 4);
            float b4[4] = {bv.x, bv.y, bv.z, bv.w};
#pragma unroll
            for (int i = 0; i < 4; i++)
#pragma unroll
                for (int j = 0; j < 4; j++) s[i][j] = fmaf(a4[i], b4[j], s[i][j]);
        }

#pragma unroll
        for (int i = 0; i < 4; i++) {
            float4 bb = *(const float4*)(biasRow + (size_t)(4 * ty + i) * NSEQ + kt * 64 + 4 * tx);
            float b4[4] = {bb.x, bb.y, bb.z, bb.w};
            float rm = -1e30f;
#pragma unroll
            for (int j = 0; j < 4; j++) {
                s[i][j] = fmaf(s[i][j], 0.125f, g3 * b4[j]);
                rm = fmaxf(rm, s[i][j]);
            }
#pragma unroll
            for (int off = 1; off < 16; off <<= 1)
                rm = fmaxf(rm, __shfl_xor_sync(0xffffffffu, rm, off));
            float mn = fmaxf(m_i[i], rm);
            float alpha = __expf(m_i[i] - mn);
            m_i[i] = mn;
            float rs = 0.f;
#pragma unroll
            for (int j = 0; j < 4; j++) { s[i][j] = __expf(s[i][j] - mn); rs += s[i][j]; }
#pragma unroll
            for (int off = 1; off < 16; off <<= 1)
                rs += __shfl_xor_sync(0xffffffffu, rs, off);
            l_i[i] = l_i[i] * alpha + rs;
#pragma unroll
            for (int j = 0; j < 4; j++) o[i][j] *= alpha;
        }

#pragma unroll
        for (int i = 0; i < 4; i++)
#pragma unroll
            for (int j = 0; j < 4; j++) Ps[(4 * ty + i) * 65 + 4 * tx + j] = s[i][j];
        __syncthreads();

#pragma unroll 8
        for (int kk = 0; kk < 64; kk++) {
            float a4[4];
#pragma unroll
            for (int i = 0; i < 4; i++) a4[i] = Ps[(4 * ty + i) * 65 + kk];
            float4 bv = *(const float4*)(Vs + kk * 64 + 4 * tx);
            float b4[4] = {bv.x, bv.y, bv.z, bv.w};
#pragma unroll
            for (int i = 0; i < 4; i++)
#pragma unroll
                for (int j = 0; j < 4; j++) o[i][j] = fmaf(a4[i], b4[j], o[i][j]);
        }
    }

    float* op = g_att + ((size_t)b * NSEQ + q0) * DMOD + h * HDIM;
#pragma unroll
    for (int i = 0; i < 4; i++) {
        float inv = 1.f / l_i[i];
        float4 w = make_float4(o[i][0] * inv, o[i][1] * inv, o[i][2] * inv, o[i][3] * inv);
        *(float4*)(op + (size_t)(4 * ty + i) * DMOD + 4 * tx) = w;
    }
}

// ---------------- launch ----------------
extern "C" void kernel_launch(void* const* d_in, const int* in_sizes, int n_in,
                              void* d_out, int out_size)
{
    (void)in_sizes; (void)n_in; (void)out_size;
    const float* x    = (const float*)d_in[0];
    const float* cm   = (const float*)d_in[1];
    const float* im   = (const float*)d_in[2];
    const float* wqkv = (const float*)d_in[3];
    const float* wout = (const float*)d_in[4];
    const float* qnw  = (const float*)d_in[5];
    const float* knw  = (const float*)d_in[6];
    const float* gate = (const float*)d_in[7];
    float* out = (float*)d_out;

    void *attp, *xh, *xl, *wqh, *wql, *woh, *wol, *ah2, *al2;
    cudaGetSymbolAddress(&attp, g_att);
    cudaGetSymbolAddress(&xh, gXh);   cudaGetSymbolAddress(&xl, gXl);
    cudaGetSymbolAddress(&wqh, gWqh); cudaGetSymbolAddress(&wql, gWql);
    cudaGetSymbolAddress(&woh, gWoh); cudaGetSymbolAddress(&wol, gWol);
    cudaGetSymbolAddress(&ah2, gAh2); cudaGetSymbolAddress(&al2, gAl2);

    cudaFuncSetAttribute(attn_kernel, cudaFuncAttributeMaxDynamicSharedMemorySize, ATTN_SMEM);
    cudaFuncSetAttribute(gemm_hmma<0>, cudaFuncAttributeMaxDynamicSharedMemorySize, GEMM_SMEM);
    cudaFuncSetAttribute(gemm_hmma<1>, cudaFuncAttributeMaxDynamicSharedMemorySize, GEMM_SMEM);

    const int M = BB * NSEQ;   // 4096

    // 1) split-convert x and weights into blocked swizzled bf16 hi/lo
    conv_split_kernel<<<(4096 * 1024 / 8) / 256, 256>>>(x,    (__nv_bfloat16*)xh,  (__nv_bfloat16*)xl,  1024);
    conv_split_kernel<<<(3072 * 1024 / 8) / 256, 256>>>(wqkv, (__nv_bfloat16*)wqh, (__nv_bfloat16*)wql, 1024);
    conv_split_kernel<<<(1024 * 1024 / 8) / 256, 256>>>(wout, (__nv_bfloat16*)woh, (__nv_bfloat16*)wol, 1024);

    // 2) QKV projection on HMMA tensor cores (head-scatter epilogue)
    gemm_hmma<1><<<dim3(3 * DMOD / 128, M / 128), 256, GEMM_SMEM>>>(
        (const char*)xh, (const char*)xl, (const char*)wqh, (const char*)wql,
        nullptr, 1024 / 64, 3 * DMOD);

    // 3) RMSNorm q and k
    rmsnorm_kernel<<<(2 * BB * NH * NSEQ * 32) / 256, 256>>>(qnw, knw);
    // 4) bias precompute
    bias_kernel<<<BB * NSEQ, 256>>>(cm, im);
    // 5) fused attention
    attn_kernel<<<dim3(NSEQ / 64, BB * NH), 256, ATTN_SMEM>>>(gate);

    // 6) split-convert attention output, then out-projection into d_out
    conv_split_kernel<<<(4096 * 1024 / 8) / 256, 256>>>((const float*)attp,
        (__nv_bfloat16*)ah2, (__nv_bfloat16*)al2, 1024);
    gemm_hmma<0><<<dim3(DMOD / 128, M / 128), 256, GEMM_SMEM>>>(
        (const char*)ah2, (const char*)al2, (const char*)woh, (const char*)wol,
        out, 1024 / 64, DMOD);
}

// round 5
// speedup vs baseline: 2.5002x; 1.6865x over previous
#include <cuda_runtime.h>
#include <cuda_bf16.h>
#include <math.h>
#include <stdint.h>

#define BB   2
#define NSEQ 2048
#define DMOD 1024
#define NH   16
#define HDIM 64
#define NC   4
#define BH   (BB * NH)

// ---------------- scratch (device globals; no allocation allowed) ----------------
__device__ float g_q[(size_t)BB * NH * NSEQ * HDIM];
__device__ float g_k[(size_t)BB * NH * NSEQ * HDIM];
__device__ float g_v[(size_t)BB * NH * NSEQ * HDIM];
__device__ float g_att[(size_t)BB * NSEQ * DMOD];
__device__ float g_bias[(size_t)BB * NSEQ * NSEQ];

// bf16 split operands for the GEMMs, pre-swizzled 128x64 SW128 tiles (16KB)
__device__ __nv_bfloat16 gXh[(size_t)4096 * 1024];
__device__ __nv_bfloat16 gXl[(size_t)4096 * 1024];
__device__ __nv_bfloat16 gWqh[(size_t)3072 * 1024];
__device__ __nv_bfloat16 gWql[(size_t)3072 * 1024];
__device__ __nv_bfloat16 gWoh[(size_t)1024 * 1024];
__device__ __nv_bfloat16 gWol[(size_t)1024 * 1024];
__device__ __nv_bfloat16 gAh2[(size_t)4096 * 1024];
__device__ __nv_bfloat16 gAl2[(size_t)4096 * 1024];

// attention operands: Q/K normed hi/lo in 128x64 tiles; V^T hi/lo in 64x64 tiles
__device__ __nv_bfloat16 gQh[(size_t)BH * NSEQ * HDIM];
__device__ __nv_bfloat16 gQl[(size_t)BH * NSEQ * HDIM];
__device__ __nv_bfloat16 gKh[(size_t)BH * NSEQ * HDIM];
__device__ __nv_bfloat16 gKl[(size_t)BH * NSEQ * HDIM];
__device__ __nv_bfloat16 gVth[(size_t)BH * NSEQ * HDIM];
__device__ __nv_bfloat16 gVtl[(size_t)BH * NSEQ * HDIM];

// ---------------- PTX helpers (base sm_103-legal only) ----------------
__device__ __forceinline__ uint32_t smem_u32(const void* p) {
    uint32_t a;
    asm("{ .reg .u64 t; cvta.to.shared.u64 t, %1; cvt.u32.u64 %0, t; }" : "=r"(a) : "l"(p));
    return a;
}

#define CP_ASYNC16(dst, src) \
    asm volatile("cp.async.cg.shared.global [%0], [%1], 16;" :: "r"(dst), "l"(src) : "memory")
#define CP_COMMIT() asm volatile("cp.async.commit_group;" ::: "memory")
#define CP_WAIT0()  asm volatile("cp.async.wait_group 0;" ::: "memory")
#define CP_WAIT1()  asm volatile("cp.async.wait_group 1;" ::: "memory")

#define LDMX4(r, a) \
    asm volatile("ldmatrix.sync.aligned.m8n8.x4.shared.b16 {%0,%1,%2,%3}, [%4];" \
        : "=r"((r)[0]), "=r"((r)[1]), "=r"((r)[2]), "=r"((r)[3]) : "r"(a))

__device__ __forceinline__ void mma_bf16(float* d, uint32_t a0, uint32_t a1,
                                         uint32_t a2, uint32_t a3,
                                         uint32_t b0, uint32_t b1) {
    asm volatile(
        "mma.sync.aligned.m16n8k16.row.col.f32.bf16.bf16.f32 "
        "{%0,%1,%2,%3},{%4,%5,%6,%7},{%8,%9},{%0,%1,%2,%3};"
        : "+f"(d[0]), "+f"(d[1]), "+f"(d[2]), "+f"(d[3])
        : "r"(a0), "r"(a1), "r"(a2), "r"(a3), "r"(b0), "r"(b1));
}

// pack {lo, hi} floats -> bf16x2 (rn)
__device__ __forceinline__ uint32_t pack2_bf16(float lo, float hi) {
    uint32_t r;
    asm("cvt.rn.bf16x2.f32 %0, %1, %2;" : "=r"(r) : "f"(hi), "f"(lo));
    return r;
}
// pack truncated-hi bf16 of two floats: low half = hi16(u0), high = hi16(u1)
__device__ __forceinline__ uint32_t pack2_hi(uint32_t u0, uint32_t u1) {
    uint32_t r;
    asm("prmt.b32 %0, %1, %2, 0x7632;" : "=r"(r) : "r"(u0), "r"(u1));
    return r;
}

// ---------------- split-conversion: fp32 row-major -> blocked swizzled bf16 hi/lo ----------------
__global__ void __launch_bounds__(256)
conv_split_kernel(const float* __restrict__ src, __nv_bfloat16* __restrict__ dh,
                  __nv_bfloat16* __restrict__ dl, int K)
{
    size_t idx = ((size_t)blockIdx.x * 256 + threadIdx.x) * 8;
    int r  = (int)(idx / K);
    int c0 = (int)(idx % K);
    float4 v0 = *(const float4*)(src + idx);
    float4 v1 = *(const float4*)(src + idx + 4);
    float f[8] = {v0.x, v0.y, v0.z, v0.w, v1.x, v1.y, v1.z, v1.w};
    __nv_bfloat16 h[8], l[8];
#pragma unroll
    for (int i = 0; i < 8; i++) {
        h[i] = __float2bfloat16(f[i]);
        l[i] = __float2bfloat16(f[i] - __bfloat162float(h[i]));
    }
    int rt = r >> 7, lr = r & 127, ch = c0 >> 6, lc = c0 & 63;
    size_t tile = (size_t)rt * (K >> 6) + ch;
    uint32_t off = lr * 128 + lc * 2;
    uint32_t sw = off ^ ((off >> 3) & 0x70);
    size_t db = tile * 16384 + sw;
    *(uint4*)((char*)dh + db) = *(uint4*)h;
    *(uint4*)((char*)dl + db) = *(uint4*)l;
}

// ---------------- HMMA GEMM (unchanged from round 4) ----------------
#define GEMM_SMEM (2 * 4 * 16384)

template <int MODE>
__global__ void __launch_bounds__(256)
gemm_hmma(const char* __restrict__ Ah, const char* __restrict__ Al,
          const char* __restrict__ Bh, const char* __restrict__ Bl,
          float* __restrict__ Cout, int KC, int Nt)
{
    extern __shared__ char smraw[];
    const uint32_t smemS = smem_u32(smraw);
    const int tid  = threadIdx.x;
    const int lane = tid & 31;
    const int warp = tid >> 5;
    const int wm = warp & 3;
    const int wn = warp >> 2;

    const size_t tA0 = (size_t)blockIdx.y * KC * 16384;
    const size_t tB0 = (size_t)blockIdx.x * KC * 16384;

    float acc[2][8][4];
#pragma unroll
    for (int i = 0; i < 2; i++)
#pragma unroll
        for (int j = 0; j < 8; j++)
#pragma unroll
            for (int t = 0; t < 4; t++) acc[i][j][t] = 0.f;

    const int lrow = lane & 15;
    const int cb   = (lane >> 4) << 4;

    {
        const char* s0 = Ah + tA0 + tid * 16;
        const char* s1 = Al + tA0 + tid * 16;
        const char* s2 = Bh + tB0 + tid * 16;
        const char* s3 = Bl + tB0 + tid * 16;
        uint32_t d0 = smemS + tid * 16;
#pragma unroll
        for (int i = 0; i < 4; i++) {
            CP_ASYNC16(d0 + 0 * 16384 + i * 4096, s0 + i * 4096);
            CP_ASYNC16(d0 + 1 * 16384 + i * 4096, s1 + i * 4096);
            CP_ASYNC16(d0 + 2 * 16384 + i * 4096, s2 + i * 4096);
            CP_ASYNC16(d0 + 3 * 16384 + i * 4096, s3 + i * 4096);
        }
        CP_COMMIT();
    }

    for (int kc = 0; kc < KC; kc++) {
        __syncthreads();
        if (kc + 1 < KC) {
            size_t go = (size_t)(kc + 1) * 16384;
            const char* s0 = Ah + tA0 + go + tid * 16;
            const char* s1 = Al + tA0 + go + tid * 16;
            const char* s2 = Bh + tB0 + go + tid * 16;
            const char* s3 = Bl + tB0 + go + tid * 16;
            uint32_t d0 = smemS + ((kc + 1) & 1) * 65536 + tid * 16;
#pragma unroll
            for (int i = 0; i < 4; i++) {
                CP_ASYNC16(d0 + 0 * 16384 + i * 4096, s0 + i * 4096);
                CP_ASYNC16(d0 + 1 * 16384 + i * 4096, s1 + i * 4096);
                CP_ASYNC16(d0 + 2 * 16384 + i * 4096, s2 + i * 4096);
                CP_ASYNC16(d0 + 3 * 16384 + i * 4096, s3 + i * 4096);
            }
            CP_COMMIT();
            CP_WAIT1();
        } else {
            CP_WAIT0();
        }
        __syncthreads();

        uint32_t buf = smemS + (kc & 1) * 65536;
        uint32_t aHs = buf, aLs = buf + 16384, bHs = buf + 32768, bLs = buf + 49152;

#pragma unroll
        for (int ks = 0; ks < 4; ks++) {
            const int cbyte = ks * 32 + cb;
            uint32_t ah[2][4], al[2][4];
#pragma unroll
            for (int mf = 0; mf < 2; mf++) {
                int row = wm * 32 + mf * 16 + lrow;
                uint32_t off = row * 128 + cbyte;
                uint32_t sw = off ^ ((row & 7) << 4);
                LDMX4(ah[mf], aHs + sw);
                LDMX4(al[mf], aLs + sw);
            }
#pragma unroll
            for (int nf2 = 0; nf2 < 4; nf2++) {
                int row = wn * 64 + nf2 * 16 + lrow;
                uint32_t off = row * 128 + cbyte;
                uint32_t sw = off ^ ((row & 7) << 4);
                uint32_t bh[4], bl[4];
                LDMX4(bh, bHs + sw);
                LDMX4(bl, bLs + sw);
#pragma unroll
                for (int mf = 0; mf < 2; mf++) {
                    float* d0 = acc[mf][2 * nf2];
                    float* d1 = acc[mf][2 * nf2 + 1];
                    mma_bf16(d0, ah[mf][0], ah[mf][1], ah[mf][2], ah[mf][3], bh[0], bh[2]);
                    mma_bf16(d0, ah[mf][0], ah[mf][1], ah[mf][2], ah[mf][3], bl[0], bl[2]);
                    mma_bf16(d0, al[mf][0], al[mf][1], al[mf][2], al[mf][3], bh[0], bh[2]);
                    mma_bf16(d1, ah[mf][0], ah[mf][1], ah[mf][2], ah[mf][3], bh[1], bh[3]);
                    mma_bf16(d1, ah[mf][0], ah[mf][1], ah[mf][2], ah[mf][3], bl[1], bl[3]);
                    mma_bf16(d1, al[mf][0], al[mf][1], al[mf][2], al[mf][3], bh[1], bh[3]);
                }
            }
        }
    }

    const int m0 = blockIdx.y * 128 + wm * 32;
    const int n0 = blockIdx.x * 128 + wn * 64;
#pragma unroll
    for (int mf = 0; mf < 2; mf++) {
#pragma unroll
        for (int nf = 0; nf < 8; nf++) {
            int m = m0 + mf * 16 + (lane >> 2);
            int n = n0 + nf * 8 + (lane & 3) * 2;
            float2 v0 = make_float2(acc[mf][nf][0], acc[mf][nf][1]);
            float2 v1 = make_float2(acc[mf][nf][2], acc[mf][nf][3]);
            if (MODE == 0) {
                *(float2*)(Cout + (size_t)m * Nt + n)       = v0;
                *(float2*)(Cout + (size_t)(m + 8) * Nt + n) = v1;
            } else {
                int which = n >> 10;
                int rem = n & 1023;
                int h = rem >> 6, dd = rem & 63;
                float* dst = (which == 0) ? g_q : (which == 1) ? g_k : g_v;
                int bb = m >> 11, nn = m & 2047;
                *(float2*)&dst[(((size_t)(bb * NH + h)) * NSEQ + nn) * HDIM + dd] = v0;
                bb = (m + 8) >> 11; nn = (m + 8) & 2047;
                *(float2*)&dst[(((size_t)(bb * NH + h)) * NSEQ + nn) * HDIM + dd] = v1;
            }
        }
    }
}

// ---------------- RMSNorm q,k -> bf16 hi/lo swizzled tiles ----------------
__global__ void __launch_bounds__(256)
rmsnorm_split_kernel(const float* __restrict__ qw, const float* __restrict__ kw)
{
    int gw   = (blockIdx.x * 256 + threadIdx.x) >> 5;
    int lane = threadIdx.x & 31;
    const int ROWS = BH * NSEQ;
    const float* src; const float* w; char* dh; char* dl; int row;
    if (gw < ROWS) { src = g_q; w = qw; dh = (char*)gQh; dl = (char*)gQl; row = gw; }
    else           { src = g_k; w = kw; dh = (char*)gKh; dl = (char*)gKl; row = gw - ROWS; }
    const float* p = src + (size_t)row * HDIM;
    float v0 = p[lane], v1 = p[lane + 32];
    float s = v0 * v0 + v1 * v1;
#pragma unroll
    for (int o = 16; o > 0; o >>= 1) s += __shfl_xor_sync(0xffffffffu, s, o);
    float r = rsqrtf(s * (1.0f / HDIM) + 1e-6f);
    float a0 = v0 * r * w[lane];
    float a1 = v1 * r * w[lane + 32];

    int tile = row >> 7, lr = row & 127;
    size_t tb = (size_t)tile * 16384;
    uint32_t x = (lr & 7) << 4;
#pragma unroll
    for (int g = 0; g < 2; g++) {
        float val = (g == 0) ? a0 : a1;
        int col = lane + g * 32;
        uint32_t off = lr * 128 + col * 2;
        uint32_t sw = off ^ x;
        uint32_t u = __float_as_uint(val);
        *(unsigned short*)(dh + tb + sw) = (unsigned short)(u >> 16);
        float lo = val - __uint_as_float(u & 0xFFFF0000u);
        __nv_bfloat16 lb = __float2bfloat16(lo);
        *(unsigned short*)(dl + tb + sw) = *(unsigned short*)&lb;
    }
}

// ---------------- V transpose + split: g_v[bh][seq][64] -> V^T 64x64 swizzled tiles ----------------
__global__ void __launch_bounds__(256)
vsplit_kernel()
{
    __shared__ float stg[64][65];
    const int kt = blockIdx.x, bh = blockIdx.y;
    const int tid = threadIdx.x;
    {
        int s = tid >> 2, d0 = (tid & 3) * 16;
        const float* vp = g_v + ((size_t)bh * NSEQ + kt * 64 + s) * HDIM + d0;
#pragma unroll
        for (int i = 0; i < 4; i++) {
            float4 v = *(const float4*)(vp + i * 4);
            stg[s][d0 + i * 4 + 0] = v.x;
            stg[s][d0 + i * 4 + 1] = v.y;
            stg[s][d0 + i * 4 + 2] = v.z;
            stg[s][d0 + i * 4 + 3] = v.w;
        }
    }
    __syncthreads();
    {
        int dR = tid >> 2, c0 = (tid & 3) * 16;
        uint32_t hw[8], lw[8];
#pragma unroll
        for (int j = 0; j < 8; j++) {
            float f0 = stg[c0 + 2 * j][dR];
            float f1 = stg[c0 + 2 * j + 1][dR];
            uint32_t u0 = __float_as_uint(f0), u1 = __float_as_uint(f1);
            hw[j] = pack2_hi(u0, u1);
            float l0 = f0 - __uint_as_float(u0 & 0xFFFF0000u);
            float l1 = f1 - __uint_as_float(u1 & 0xFFFF0000u);
            lw[j] = pack2_bf16(l0, l1);
        }
        size_t tb = ((size_t)bh * 32 + kt) * 8192;
        uint32_t off0 = dR * 128 + c0 * 2;
        uint32_t x = (dR & 7) << 4;
        *(uint4*)((char*)gVth + tb + (off0 ^ x))        = make_uint4(hw[0], hw[1], hw[2], hw[3]);
        *(uint4*)((char*)gVth + tb + ((off0 + 16) ^ x)) = make_uint4(hw[4], hw[5], hw[6], hw[7]);
        *(uint4*)((char*)gVtl + tb + (off0 ^ x))        = make_uint4(lw[0], lw[1], lw[2], lw[3]);
        *(uint4*)((char*)gVtl + tb + ((off0 + 16) ^ x)) = make_uint4(lw[4], lw[5], lw[6], lw[7]);
    }
}

// ---------------- bias precompute (unchanged) ----------------
__global__ void __launch_bounds__(256)
bias_kernel(const float* __restrict__ cm, const float* __restrict__ im)
{
    int bq = blockIdx.x;
    int b = bq / NSEQ, q = bq % NSEQ;
    const float* cmb = cm + (size_t)b * NC * NSEQ;
    float c0 = cmb[q], c1 = cmb[NSEQ + q], c2 = cmb[2 * NSEQ + q], c3 = cmb[3 * NSEQ + q];

    float mx = 0.f;
    for (int k = threadIdx.x; k < NSEQ; k += 256) {
        float s = c0 * cmb[k] + c1 * cmb[NSEQ + k] + c2 * cmb[2 * NSEQ + k] + c3 * cmb[3 * NSEQ + k];
        mx = fmaxf(mx, s);
    }
    __shared__ float red[8];
#pragma unroll
    for (int o = 16; o > 0; o >>= 1) mx = fmaxf(mx, __shfl_xor_sync(0xffffffffu, mx, o));
    if ((threadIdx.x & 31) == 0) red[threadIdx.x >> 5] = mx;
    __syncthreads();
    if (threadIdx.x == 0) {
        float m = red[0];
#pragma unroll
        for (int wN = 1; wN < 8; wN++) m = fmaxf(m, red[wN]);
        red[0] = fmaxf(m, 1e-6f);
    }
    __syncthreads();
    float inv = 1.f / red[0];
    const float* imr = im + (size_t)bq * NSEQ;
    float* br = g_bias + (size_t)bq * NSEQ;
    for (int k = threadIdx.x; k < NSEQ; k += 256) {
        float s = c0 * cmb[k] + c1 * cmb[NSEQ + k] + c2 * cmb[2 * NSEQ + k] + c3 * cmb[3 * NSEQ + k];
        br[k] = 2.f * s * inv - 1.f + 0.3f * imr[k];
    }
}

// ---------------- HMMA flash attention ----------------
// grid (NSEQ/128, BH), 256 threads / 8 warps; warp owns 16 q-rows x 64 keys.
// smem: QH 16K | QL 16K | 2 x (KH 8K | KL 8K | VTH 8K | VTL 8K)
#define ATTN2_SMEM 98304

__global__ void __launch_bounds__(256)
attn2_kernel(const float* __restrict__ gate)
{
    extern __shared__ char smraw[];
    const uint32_t S = smem_u32(smraw);
    const int tid = threadIdx.x, lane = tid & 31, warp = tid >> 5;
    const int bh = blockIdx.y, b = bh >> 4, h = bh & 15;
    const int qt = blockIdx.x, q0 = qt * 128;
    const float g3 = 3.f * fminf(fmaxf(gate[h], 0.f), 1.f);
    const int lrow = lane & 15, cb = (lane >> 4) << 4;
    const int wrow = warp * 16;

    // prologue: Q tile (group 0)
    {
        size_t qoff = ((size_t)(bh * 16 + qt)) * 16384 + tid * 16;
        uint32_t d = S + tid * 16;
#pragma unroll
        for (int i = 0; i < 4; i++) {
            CP_ASYNC16(d + i * 4096,         (const char*)gQh + qoff + i * 4096);
            CP_ASYNC16(d + 16384 + i * 4096, (const char*)gQl + qoff + i * 4096);
        }
        CP_COMMIT();
    }
    // prologue: KV tile 0 (group 1)
    {
        size_t koff = ((size_t)(bh * 16)) * 16384 + tid * 16;
        size_t voff = ((size_t)(bh * 32)) * 8192 + tid * 16;
        uint32_t d = S + 32768 + tid * 16;
#pragma unroll
        for (int i = 0; i < 2; i++) {
            CP_ASYNC16(d + 0     + i * 4096, (const char*)gKh  + koff + i * 4096);
            CP_ASYNC16(d + 8192  + i * 4096, (const char*)gKl  + koff + i * 4096);
            CP_ASYNC16(d + 16384 + i * 4096, (const char*)gVth + voff + i * 4096);
            CP_ASYNC16(d + 24576 + i * 4096, (const char*)gVtl + voff + i * 4096);
        }
        CP_COMMIT();
    }

    uint32_t qh[4][4], ql[4][4];
    float o[8][4];
#pragma unroll
    for (int nf = 0; nf < 8; nf++)
#pragma unroll
        for (int t = 0; t < 4; t++) o[nf][t] = 0.f;
    float m0r = -1e30f, m1r = -1e30f, l0r = 0.f, l1r = 0.f;

    const int r0l = lane >> 2;
    const float* bias0 = g_bias + ((size_t)(b * NSEQ + q0 + wrow + r0l)) * NSEQ;
    const float* bias1 = bias0 + 8 * NSEQ;

    for (int kt = 0; kt < 32; kt++) {
        __syncthreads();
        if (kt + 1 < 32) {
            int k2 = kt + 1;
            size_t koff = ((size_t)(bh * 16 + (k2 >> 1))) * 16384 + (size_t)(k2 & 1) * 8192 + tid * 16;
            size_t voff = ((size_t)(bh * 32 + k2)) * 8192 + tid * 16;
            uint32_t d = S + 32768 + (k2 & 1) * 32768 + tid * 16;
#pragma unroll
            for (int i = 0; i < 2; i++) {
                CP_ASYNC16(d + 0     + i * 4096, (const char*)gKh  + koff + i * 4096);
                CP_ASYNC16(d + 8192  + i * 4096, (const char*)gKl  + koff + i * 4096);
                CP_ASYNC16(d + 16384 + i * 4096, (const char*)gVth + voff + i * 4096);
                CP_ASYNC16(d + 24576 + i * 4096, (const char*)gVtl + voff + i * 4096);
            }
            CP_COMMIT();
            CP_WAIT1();
        } else {
            CP_WAIT0();
        }
        __syncthreads();

        if (kt == 0) {
#pragma unroll
            for (int ks = 0; ks < 4; ks++) {
                uint32_t off = (wrow + lrow) * 128 + ks * 32 + cb;
                uint32_t sw = off ^ (((wrow + lrow) & 7) << 4);
                LDMX4(qh[ks], S + sw);
                LDMX4(ql[ks], S + 16384 + sw);
            }
        }

        uint32_t buf = S + 32768 + (kt & 1) * 32768;

        // S = Q K^T (3-term split)
        float sf[8][4];
#pragma unroll
        for (int nf = 0; nf < 8; nf++)
#pragma unroll
            for (int t = 0; t < 4; t++) sf[nf][t] = 0.f;

#pragma unroll
        for (int ks = 0; ks < 4; ks++) {
#pragma unroll
            for (int nf2 = 0; nf2 < 4; nf2++) {
                uint32_t off = (nf2 * 16 + lrow) * 128 + ks * 32 + cb;
                uint32_t sw = off ^ ((lrow & 7) << 4);
                uint32_t kh_[4], kl_[4];
                LDMX4(kh_, buf + sw);
                LDMX4(kl_, buf + 8192 + sw);
                float* d0 = sf[2 * nf2];
                float* d1 = sf[2 * nf2 + 1];
                mma_bf16(d0, qh[ks][0], qh[ks][1], qh[ks][2], qh[ks][3], kh_[0], kh_[2]);
                mma_bf16(d0, qh[ks][0], qh[ks][1], qh[ks][2], qh[ks][3], kl_[0], kl_[2]);
                mma_bf16(d0, ql[ks][0], ql[ks][1], ql[ks][2], ql[ks][3], kh_[0], kh_[2]);
                mma_bf16(d1, qh[ks][0], qh[ks][1], qh[ks][2], qh[ks][3], kh_[1], kh_[3]);
                mma_bf16(d1, qh[ks][0], qh[ks][1], qh[ks][2], qh[ks][3], kl_[1], kl_[3]);
                mma_bf16(d1, ql[ks][0], ql[ks][1], ql[ks][2], ql[ks][3], kh_[1], kh_[3]);
            }
        }

        // scale + gated bias + online softmax (rows r0l, r0l+8)
        int colbase = kt * 64 + 2 * (lane & 3);
        float rm0 = -1e30f, rm1 = -1e30f;
#pragma unroll
        for (int nf = 0; nf < 8; nf++) {
            float2 bb0 = *(const float2*)(bias0 + colbase + nf * 8);
            float2 bb1 = *(const float2*)(bias1 + colbase + nf * 8);
            sf[nf][0] = fmaf(sf[nf][0], 0.125f, g3 * bb0.x);
            sf[nf][1] = fmaf(sf[nf][1], 0.125f, g3 * bb0.y);
            sf[nf][2] = fmaf(sf[nf][2], 0.125f, g3 * bb1.x);
            sf[nf][3] = fmaf(sf[nf][3], 0.125f, g3 * bb1.y);
            rm0 = fmaxf(rm0, fmaxf(sf[nf][0], sf[nf][1]));
            rm1 = fmaxf(rm1, fmaxf(sf[nf][2], sf[nf][3]));
        }
        rm0 = fmaxf(rm0, __shfl_xor_sync(0xffffffffu, rm0, 1));
        rm0 = fmaxf(rm0, __shfl_xor_sync(0xffffffffu, rm0, 2));
        rm1 = fmaxf(rm1, __shfl_xor_sync(0xffffffffu, rm1, 1));
        rm1 = fmaxf(rm1, __shfl_xor_sync(0xffffffffu, rm1, 2));

        float mn0 = fmaxf(m0r, rm0), mn1 = fmaxf(m1r, rm1);
        float al0 = __expf(m0r - mn0), al1 = __expf(m1r - mn1);
        m0r = mn0; m1r = mn1;
        float rs0 = 0.f, rs1 = 0.f;
#pragma unroll
        for (int nf = 0; nf < 8; nf++) {
            sf[nf][0] = __expf(sf[nf][0] - mn0);
            sf[nf][1] = __expf(sf[nf][1] - mn0);
            sf[nf][2] = __expf(sf[nf][2] - mn1);
            sf[nf][3] = __expf(sf[nf][3] - mn1);
            rs0 += sf[nf][0] + sf[nf][1];
            rs1 += sf[nf][2] + sf[nf][3];
        }
        rs0 += __shfl_xor_sync(0xffffffffu, rs0, 1);
        rs0 += __shfl_xor_sync(0xffffffffu, rs0, 2);
        rs1 += __shfl_xor_sync(0xffffffffu, rs1, 1);
        rs1 += __shfl_xor_sync(0xffffffffu, rs1, 2);
        l0r = l0r * al0 + rs0;
        l1r = l1r * al1 + rs1;
#pragma unroll
        for (int nf = 0; nf < 8; nf++) {
            o[nf][0] *= al0; o[nf][1] *= al0;
            o[nf][2] *= al1; o[nf][3] *= al1;
        }

        // O += P V (P fragments built in registers from S fragments, hi/lo split)
#pragma unroll
        for (int kk = 0; kk < 4; kk++) {
            const int na = 2 * kk, nb = 2 * kk + 1;
            uint32_t u0 = __float_as_uint(sf[na][0]), u1 = __float_as_uint(sf[na][1]);
            uint32_t u2 = __float_as_uint(sf[na][2]), u3 = __float_as_uint(sf[na][3]);
            uint32_t w0 = __float_as_uint(sf[nb][0]), w1 = __float_as_uint(sf[nb][1]);
            uint32_t w2 = __float_as_uint(sf[nb][2]), w3 = __float_as_uint(sf[nb][3]);
            uint32_t ph_[4], pl_[4];
            ph_[0] = pack2_hi(u0, u1);
            ph_[1] = pack2_hi(u2, u3);
            ph_[2] = pack2_hi(w0, w1);
            ph_[3] = pack2_hi(w2, w3);
            pl_[0] = pack2_bf16(sf[na][0] - __uint_as_float(u0 & 0xFFFF0000u),
                                sf[na][1] - __uint_as_float(u1 & 0xFFFF0000u));
            pl_[1] = pack2_bf16(sf[na][2] - __uint_as_float(u2 & 0xFFFF0000u),
                                sf[na][3] - __uint_as_float(u3 & 0xFFFF0000u));
            pl_[2] = pack2_bf16(sf[nb][0] - __uint_as_float(w0 & 0xFFFF0000u),
                                sf[nb][1] - __uint_as_float(w1 & 0xFFFF0000u));
            pl_[3] = pack2_bf16(sf[nb][2] - __uint_as_float(w2 & 0xFFFF0000u),
                                sf[nb][3] - __uint_as_float(w3 & 0xFFFF0000u));
#pragma unroll
            for (int nf2 = 0; nf2 < 4; nf2++) {
                uint32_t off = (nf2 * 16 + lrow) * 128 + kk * 32 + cb;
                uint32_t sw = off ^ ((lrow & 7) << 4);
                uint32_t vh_[4], vl_[4];
                LDMX4(vh_, buf + 16384 + sw);
                LDMX4(vl_, buf + 24576 + sw);
                float* d0 = o[2 * nf2];
                float* d1 = o[2 * nf2 + 1];
                mma_bf16(d0, ph_[0], ph_[1], ph_[2], ph_[3], vh_[0], vh_[2]);
                mma_bf16(d0, ph_[0], ph_[1], ph_[2], ph_[3], vl_[0], vl_[2]);
                mma_bf16(d0, pl_[0], pl_[1], pl_[2], pl_[3], vh_[0], vh_[2]);
                mma_bf16(d1, ph_[0], ph_[1], ph_[2], ph_[3], vh_[1], vh_[3]);
                mma_bf16(d1, ph_[0], ph_[1], ph_[2], ph_[3], vl_[1], vl_[3]);
                mma_bf16(d1, pl_[0], pl_[1], pl_[2], pl_[3], vh_[1], vh_[3]);
            }
        }
    }

    // epilogue: normalize + write (B,N,D)
    float i0 = 1.f / l0r, i1 = 1.f / l1r;
    float* op0 = g_att + ((size_t)(b * NSEQ + q0 + wrow + r0l)) * DMOD + h * HDIM + 2 * (lane & 3);
    float* op1 = op0 + (size_t)8 * DMOD;
#pragma unroll
    for (int nf = 0; nf < 8; nf++) {
        *(float2*)(op0 + nf * 8) = make_float2(o[nf][0] * i0, o[nf][1] * i0);
        *(float2*)(op1 + nf * 8) = make_float2(o[nf][2] * i1, o[nf][3] * i1);
    }
}

// ---------------- launch ----------------
extern "C" void kernel_launch(void* const* d_in, const int* in_sizes, int n_in,
                              void* d_out, int out_size)
{
    (void)in_sizes; (void)n_in; (void)out_size;
    const float* x    = (const float*)d_in[0];
    const float* cm   = (const float*)d_in[1];
    const float* im   = (const float*)d_in[2];
    const float* wqkv = (const float*)d_in[3];
    const float* wout = (const float*)d_in[4];
    const float* qnw  = (const float*)d_in[5];
    const float* knw  = (const float*)d_in[6];
    const float* gate = (const float*)d_in[7];
    float* out = (float*)d_out;

    void *attp, *xh, *xl, *wqh, *wql, *woh, *wol, *ah2, *al2;
    cudaGetSymbolAddress(&attp, g_att);
    cudaGetSymbolAddress(&xh, gXh);   cudaGetSymbolAddress(&xl, gXl);
    cudaGetSymbolAddress(&wqh, gWqh); cudaGetSymbolAddress(&wql, gWql);
    cudaGetSymbolAddress(&woh, gWoh); cudaGetSymbolAddress(&wol, gWol);
    cudaGetSymbolAddress(&ah2, gAh2); cudaGetSymbolAddress(&al2, gAl2);

    cudaFuncSetAttribute(attn2_kernel, cudaFuncAttributeMaxDynamicSharedMemorySize, ATTN2_SMEM);
    cudaFuncSetAttribute(gemm_hmma<0>, cudaFuncAttributeMaxDynamicSharedMemorySize, GEMM_SMEM);
    cudaFuncSetAttribute(gemm_hmma<1>, cudaFuncAttributeMaxDynamicSharedMemorySize, GEMM_SMEM);

    const int M = BB * NSEQ;   // 4096

    // 1) split-convert inputs
    conv_split_kernel<<<(4096 * 1024 / 8) / 256, 256>>>(x,    (__nv_bfloat16*)xh,  (__nv_bfloat16*)xl,  1024);
    conv_split_kernel<<<(3072 * 1024 / 8) / 256, 256>>>(wqkv, (__nv_bfloat16*)wqh, (__nv_bfloat16*)wql, 1024);
    conv_split_kernel<<<(1024 * 1024 / 8) / 256, 256>>>(wout, (__nv_bfloat16*)woh, (__nv_bfloat16*)wol, 1024);

    // 2) QKV projection (HMMA, head-scatter epilogue)
    gemm_hmma<1><<<dim3(3 * DMOD / 128, M / 128), 256, GEMM_SMEM>>>(
        (const char*)xh, (const char*)xl, (const char*)wqh, (const char*)wql,
        nullptr, 1024 / 64, 3 * DMOD);

    // 3) RMSNorm q,k -> bf16 hi/lo tiles;  V -> transposed bf16 hi/lo tiles
    rmsnorm_split_kernel<<<(2 * BH * NSEQ * 32) / 256, 256>>>(qnw, knw);
    vsplit_kernel<<<dim3(NSEQ / 64, BH), 256>>>();

    // 4) bias precompute
    bias_kernel<<<BB * NSEQ, 256>>>(cm, im);

    // 5) HMMA flash attention
    attn2_kernel<<<dim3(NSEQ / 128, BH), 256, ATTN2_SMEM>>>(gate);

    // 6) out-projection
    conv_split_kernel<<<(4096 * 1024 / 8) / 256, 256>>>((const float*)attp,
        (__nv_bfloat16*)ah2, (__nv_bfloat16*)al2, 1024);
    gemm_hmma<0><<<dim3(DMOD / 128, M / 128), 256, GEMM_SMEM>>>(
        (const char*)ah2, (const char*)al2, (const char*)woh, (const char*)wol,
        out, 1024 / 64, DMOD);
}

// round 6
// speedup vs baseline: 2.6557x; 1.0622x over previous
#include <cuda_runtime.h>
#include <cuda_bf16.h>
#include <math.h>
#include <stdint.h>

#define BB   2
#define NSEQ 2048
#define DMOD 1024
#define NH   16
#define HDIM 64
#define NC   4
#define BH   (BB * NH)

// ---------------- scratch (device globals; no allocation allowed) ----------------
__device__ float g_v[(size_t)BB * NH * NSEQ * HDIM];
__device__ float g_bias[(size_t)BB * NSEQ * NSEQ];

// bf16 split operands, pre-swizzled 128x64 SW128 tiles (16KB each)
__device__ __nv_bfloat16 gXh[(size_t)4096 * 1024];
__device__ __nv_bfloat16 gXl[(size_t)4096 * 1024];
__device__ __nv_bfloat16 gWqh[(size_t)3072 * 1024];
__device__ __nv_bfloat16 gWql[(size_t)3072 * 1024];
__device__ __nv_bfloat16 gWoh[(size_t)1024 * 1024];
__device__ __nv_bfloat16 gWol[(size_t)1024 * 1024];
__device__ __nv_bfloat16 gAh2[(size_t)4096 * 1024];
__device__ __nv_bfloat16 gAl2[(size_t)4096 * 1024];

// attention operands (q/k written by QKV epilogue; V^T by vsplit)
__device__ __nv_bfloat16 gQh[(size_t)BH * NSEQ * HDIM];
__device__ __nv_bfloat16 gQl[(size_t)BH * NSEQ * HDIM];
__device__ __nv_bfloat16 gKh[(size_t)BH * NSEQ * HDIM];
__device__ __nv_bfloat16 gKl[(size_t)BH * NSEQ * HDIM];
__device__ __nv_bfloat16 gVth[(size_t)BH * NSEQ * HDIM];
__device__ __nv_bfloat16 gVtl[(size_t)BH * NSEQ * HDIM];

// ---------------- PTX helpers (base sm_103-legal only) ----------------
__device__ __forceinline__ uint32_t smem_u32(const void* p) {
    uint32_t a;
    asm("{ .reg .u64 t; cvta.to.shared.u64 t, %1; cvt.u32.u64 %0, t; }" : "=r"(a) : "l"(p));
    return a;
}

#define CP_ASYNC16(dst, src) \
    asm volatile("cp.async.cg.shared.global [%0], [%1], 16;" :: "r"(dst), "l"(src) : "memory")
#define CP_COMMIT() asm volatile("cp.async.commit_group;" ::: "memory")
#define CP_WAIT0()  asm volatile("cp.async.wait_group 0;" ::: "memory")
#define CP_WAIT1()  asm volatile("cp.async.wait_group 1;" ::: "memory")

#define LDMX4(r, a) \
    asm volatile("ldmatrix.sync.aligned.m8n8.x4.shared.b16 {%0,%1,%2,%3}, [%4];" \
        : "=r"((r)[0]), "=r"((r)[1]), "=r"((r)[2]), "=r"((r)[3]) : "r"(a))

__device__ __forceinline__ void mma_bf16(float* d, uint32_t a0, uint32_t a1,
                                         uint32_t a2, uint32_t a3,
                                         uint32_t b0, uint32_t b1) {
    asm volatile(
        "mma.sync.aligned.m16n8k16.row.col.f32.bf16.bf16.f32 "
        "{%0,%1,%2,%3},{%4,%5,%6,%7},{%8,%9},{%0,%1,%2,%3};"
        : "+f"(d[0]), "+f"(d[1]), "+f"(d[2]), "+f"(d[3])
        : "r"(a0), "r"(a1), "r"(a2), "r"(a3), "r"(b0), "r"(b1));
}

__device__ __forceinline__ uint32_t pack2_bf16(float lo, float hi) {
    uint32_t r;
    asm("cvt.rn.bf16x2.f32 %0, %1, %2;" : "=r"(r) : "f"(hi), "f"(lo));
    return r;
}
__device__ __forceinline__ uint32_t pack2_hi(uint32_t u0, uint32_t u1) {
    uint32_t r;
    asm("prmt.b32 %0, %1, %2, 0x7632;" : "=r"(r) : "r"(u0), "r"(u1));
    return r;
}

// ---------------- split-conversion: fp32 row-major -> blocked swizzled bf16 hi/lo ----------------
__global__ void __launch_bounds__(256)
conv_split_kernel(const float* __restrict__ src, __nv_bfloat16* __restrict__ dh,
                  __nv_bfloat16* __restrict__ dl, int K)
{
    size_t idx = ((size_t)blockIdx.x * 256 + threadIdx.x) * 8;
    int r  = (int)(idx / K);
    int c0 = (int)(idx % K);
    float4 v0 = *(const float4*)(src + idx);
    float4 v1 = *(const float4*)(src + idx + 4);
    float f[8] = {v0.x, v0.y, v0.z, v0.w, v1.x, v1.y, v1.z, v1.w};
    __nv_bfloat16 h[8], l[8];
#pragma unroll
    for (int i = 0; i < 8; i++) {
        h[i] = __float2bfloat16(f[i]);
        l[i] = __float2bfloat16(f[i] - __bfloat162float(h[i]));
    }
    int rt = r >> 7, lr = r & 127, ch = c0 >> 6, lc = c0 & 63;
    size_t tile = (size_t)rt * (K >> 6) + ch;
    uint32_t off = lr * 128 + lc * 2;
    uint32_t sw = off ^ ((off >> 3) & 0x70);
    size_t db = tile * 16384 + sw;
    *(uint4*)((char*)dh + db) = *(uint4*)h;
    *(uint4*)((char*)dl + db) = *(uint4*)l;
}

// ---------------- HMMA GEMM: 512 threads, 16 warps (8m x 2n), warp tile 16x64 ----------------
// MODE 0: row-major store to Cout.
// MODE 1: QKV epilogue — fused RMSNorm for q/k + direct bf16 hi/lo swizzled-tile writes; v -> g_v f32.
#define GEMM_SMEM (2 * 4 * 16384)

template <int MODE>
__global__ void __launch_bounds__(512)
gemm_hmma(const char* __restrict__ Ah, const char* __restrict__ Al,
          const char* __restrict__ Bh, const char* __restrict__ Bl,
          float* __restrict__ Cout, int KC, int Nt,
          const float* __restrict__ qw, const float* __restrict__ kw)
{
    extern __shared__ char smraw[];
    const uint32_t smemS = smem_u32(smraw);
    const int tid  = threadIdx.x;
    const int lane = tid & 31;
    const int warp = tid >> 5;
    const int wm = warp & 7;      // 16-row slice
    const int wn = warp >> 3;     // 64-col slice

    const size_t tA0 = (size_t)blockIdx.y * KC * 16384;
    const size_t tB0 = (size_t)blockIdx.x * KC * 16384;

    float acc[8][4];
#pragma unroll
    for (int j = 0; j < 8; j++)
#pragma unroll
        for (int t = 0; t < 4; t++) acc[j][t] = 0.f;

    const int lrow = lane & 15;
    const int cb   = (lane >> 4) << 4;

    {
        const char* s0 = Ah + tA0 + tid * 16;
        const char* s1 = Al + tA0 + tid * 16;
        const char* s2 = Bh + tB0 + tid * 16;
        const char* s3 = Bl + tB0 + tid * 16;
        uint32_t d0 = smemS + tid * 16;
#pragma unroll
        for (int i = 0; i < 2; i++) {
            CP_ASYNC16(d0 + 0 * 16384 + i * 8192, s0 + i * 8192);
            CP_ASYNC16(d0 + 1 * 16384 + i * 8192, s1 + i * 8192);
            CP_ASYNC16(d0 + 2 * 16384 + i * 8192, s2 + i * 8192);
            CP_ASYNC16(d0 + 3 * 16384 + i * 8192, s3 + i * 8192);
        }
        CP_COMMIT();
    }

    for (int kc = 0; kc < KC; kc++) {
        __syncthreads();
        if (kc + 1 < KC) {
            size_t go = (size_t)(kc + 1) * 16384;
            const char* s0 = Ah + tA0 + go + tid * 16;
            const char* s1 = Al + tA0 + go + tid * 16;
            const char* s2 = Bh + tB0 + go + tid * 16;
            const char* s3 = Bl + tB0 + go + tid * 16;
            uint32_t d0 = smemS + ((kc + 1) & 1) * 65536 + tid * 16;
#pragma unroll
            for (int i = 0; i < 2; i++) {
                CP_ASYNC16(d0 + 0 * 16384 + i * 8192, s0 + i * 8192);
                CP_ASYNC16(d0 + 1 * 16384 + i * 8192, s1 + i * 8192);
                CP_ASYNC16(d0 + 2 * 16384 + i * 8192, s2 + i * 8192);
                CP_ASYNC16(d0 + 3 * 16384 + i * 8192, s3 + i * 8192);
            }
            CP_COMMIT();
            CP_WAIT1();
        } else {
            CP_WAIT0();
        }
        __syncthreads();

        uint32_t buf = smemS + (kc & 1) * 65536;
        uint32_t aHs = buf, aLs = buf + 16384, bHs = buf + 32768, bLs = buf + 49152;

#pragma unroll
        for (int ks = 0; ks < 4; ks++) {
            const int cbyte = ks * 32 + cb;
            uint32_t ah[4], al[4];
            {
                int row = wm * 16 + lrow;
                uint32_t off = row * 128 + cbyte;
                uint32_t sw = off ^ ((row & 7) << 4);
                LDMX4(ah, aHs + sw);
                LDMX4(al, aLs + sw);
            }
#pragma unroll
            for (int nf2 = 0; nf2 < 4; nf2++) {
                int row = wn * 64 + nf2 * 16 + lrow;
                uint32_t off = row * 128 + cbyte;
                uint32_t sw = off ^ ((row & 7) << 4);
                uint32_t bh[4], bl[4];
                LDMX4(bh, bHs + sw);
                LDMX4(bl, bLs + sw);
                float* d0 = acc[2 * nf2];
                float* d1 = acc[2 * nf2 + 1];
                mma_bf16(d0, ah[0], ah[1], ah[2], ah[3], bh[0], bh[2]);
                mma_bf16(d0, ah[0], ah[1], ah[2], ah[3], bl[0], bl[2]);
                mma_bf16(d0, al[0], al[1], al[2], al[3], bh[0], bh[2]);
                mma_bf16(d1, ah[0], ah[1], ah[2], ah[3], bh[1], bh[3]);
                mma_bf16(d1, ah[0], ah[1], ah[2], ah[3], bl[1], bl[3]);
                mma_bf16(d1, al[0], al[1], al[2], al[3], bh[1], bh[3]);
            }
        }
    }

    const int r0l = lane >> 2;
    const int c2  = (lane & 3) * 2;

    if (MODE == 0) {
        const int m0 = blockIdx.y * 128 + wm * 16 + r0l;
        const int n0 = blockIdx.x * 128 + wn * 64;
#pragma unroll
        for (int nf = 0; nf < 8; nf++) {
            int n = n0 + nf * 8 + c2;
            *(float2*)(Cout + (size_t)m0 * Nt + n)       = make_float2(acc[nf][0], acc[nf][1]);
            *(float2*)(Cout + (size_t)(m0 + 8) * Nt + n) = make_float2(acc[nf][2], acc[nf][3]);
        }
    } else {
        const int j = blockIdx.x * 2 + wn;     // 64-col chunk: 0..47
        const int which = j >> 4;              // 0:q 1:k 2:v
        const int h = j & 15;
        const int m0 = blockIdx.y * 128 + wm * 16 + r0l;   // global row (token) of pair0
        const int m1 = m0 + 8;
        const int b0i = m0 >> 11, n0i = m0 & 2047;
        const int b1i = m1 >> 11, n1i = m1 & 2047;

        if (which == 2) {
            float* vb = g_v;
#pragma unroll
            for (int nf = 0; nf < 8; nf++) {
                int dd = nf * 8 + c2;
                *(float2*)&vb[(((size_t)(b0i * NH + h)) * NSEQ + n0i) * HDIM + dd] =
                    make_float2(acc[nf][0], acc[nf][1]);
                *(float2*)&vb[(((size_t)(b1i * NH + h)) * NSEQ + n1i) * HDIM + dd] =
                    make_float2(acc[nf][2], acc[nf][3]);
            }
        } else {
            const float* w = (which == 0) ? qw : kw;
            char* dh = (which == 0) ? (char*)gQh : (char*)gKh;
            char* dl = (which == 0) ? (char*)gQl : (char*)gKl;
            float ss0 = 0.f, ss1 = 0.f;
#pragma unroll
            for (int nf = 0; nf < 8; nf++) {
                ss0 += acc[nf][0] * acc[nf][0] + acc[nf][1] * acc[nf][1];
                ss1 += acc[nf][2] * acc[nf][2] + acc[nf][3] * acc[nf][3];
            }
            ss0 += __shfl_xor_sync(0xffffffffu, ss0, 1);
            ss0 += __shfl_xor_sync(0xffffffffu, ss0, 2);
            ss1 += __shfl_xor_sync(0xffffffffu, ss1, 1);
            ss1 += __shfl_xor_sync(0xffffffffu, ss1, 2);
            float r0 = rsqrtf(ss0 * (1.0f / HDIM) + 1e-6f);
            float r1 = rsqrtf(ss1 * (1.0f / HDIM) + 1e-6f);

            size_t tb0 = (((size_t)(b0i * NH + h)) * 16 + (n0i >> 7)) * 16384;
            size_t tb1 = (((size_t)(b1i * NH + h)) * 16 + (n1i >> 7)) * 16384;
            int lr0 = n0i & 127, lr1 = n1i & 127;
            uint32_t x0 = (lr0 & 7) << 4, x1 = (lr1 & 7) << 4;
#pragma unroll
            for (int nf = 0; nf < 8; nf++) {
                int dd = nf * 8 + c2;
                float2 wv = *(const float2*)(w + dd);
                float v0 = acc[nf][0] * r0 * wv.x;
                float v1 = acc[nf][1] * r0 * wv.y;
                float v2 = acc[nf][2] * r1 * wv.x;
                float v3 = acc[nf][3] * r1 * wv.y;
                uint32_t u0 = __float_as_uint(v0), u1 = __float_as_uint(v1);
                uint32_t u2 = __float_as_uint(v2), u3 = __float_as_uint(v3);
                uint32_t o0 = (lr0 * 128 + dd * 2) ^ x0;
                uint32_t o1 = (lr1 * 128 + dd * 2) ^ x1;
                *(uint32_t*)(dh + tb0 + o0) = pack2_hi(u0, u1);
                *(uint32_t*)(dh + tb1 + o1) = pack2_hi(u2, u3);
                *(uint32_t*)(dl + tb0 + o0) =
                    pack2_bf16(v0 - __uint_as_float(u0 & 0xFFFF0000u),
                               v1 - __uint_as_float(u1 & 0xFFFF0000u));
                *(uint32_t*)(dl + tb1 + o1) =
                    pack2_bf16(v2 - __uint_as_float(u2 & 0xFFFF0000u),
                               v3 - __uint_as_float(u3 & 0xFFFF0000u));
            }
        }
    }
}

// ---------------- V transpose + split: g_v[bh][seq][64] -> V^T 64x64 swizzled tiles ----------------
__global__ void __launch_bounds__(256)
vsplit_kernel()
{
    __shared__ float stg[64][65];
    const int kt = blockIdx.x, bh = blockIdx.y;
    const int tid = threadIdx.x;
    {
        int s = tid >> 2, d0 = (tid & 3) * 16;
        const float* vp = g_v + ((size_t)bh * NSEQ + kt * 64 + s) * HDIM + d0;
#pragma unroll
        for (int i = 0; i < 4; i++) {
            float4 v = *(const float4*)(vp + i * 4);
            stg[s][d0 + i * 4 + 0] = v.x;
            stg[s][d0 + i * 4 + 1] = v.y;
            stg[s][d0 + i * 4 + 2] = v.z;
            stg[s][d0 + i * 4 + 3] = v.w;
        }
    }
    __syncthreads();
    {
        int dR = tid >> 2, c0 = (tid & 3) * 16;
        uint32_t hw[8], lw[8];
#pragma unroll
        for (int j = 0; j < 8; j++) {
            float f0 = stg[c0 + 2 * j][dR];
            float f1 = stg[c0 + 2 * j + 1][dR];
            uint32_t u0 = __float_as_uint(f0), u1 = __float_as_uint(f1);
            hw[j] = pack2_hi(u0, u1);
            float l0 = f0 - __uint_as_float(u0 & 0xFFFF0000u);
            float l1 = f1 - __uint_as_float(u1 & 0xFFFF0000u);
            lw[j] = pack2_bf16(l0, l1);
        }
        size_t tb = ((size_t)bh * 32 + kt) * 8192;
        uint32_t off0 = dR * 128 + c0 * 2;
        uint32_t x = (dR & 7) << 4;
        *(uint4*)((char*)gVth + tb + (off0 ^ x))        = make_uint4(hw[0], hw[1], hw[2], hw[3]);
        *(uint4*)((char*)gVth + tb + ((off0 + 16) ^ x)) = make_uint4(hw[4], hw[5], hw[6], hw[7]);
        *(uint4*)((char*)gVtl + tb + (off0 ^ x))        = make_uint4(lw[0], lw[1], lw[2], lw[3]);
        *(uint4*)((char*)gVtl + tb + ((off0 + 16) ^ x)) = make_uint4(lw[4], lw[5], lw[6], lw[7]);
    }
}

// ---------------- bias precompute ----------------
__global__ void __launch_bounds__(256)
bias_kernel(const float* __restrict__ cm, const float* __restrict__ im)
{
    int bq = blockIdx.x;
    int b = bq / NSEQ, q = bq % NSEQ;
    const float* cmb = cm + (size_t)b * NC * NSEQ;
    float c0 = cmb[q], c1 = cmb[NSEQ + q], c2 = cmb[2 * NSEQ + q], c3 = cmb[3 * NSEQ + q];

    float mx = 0.f;
    for (int k = threadIdx.x; k < NSEQ; k += 256) {
        float s = c0 * cmb[k] + c1 * cmb[NSEQ + k] + c2 * cmb[2 * NSEQ + k] + c3 * cmb[3 * NSEQ + k];
        mx = fmaxf(mx, s);
    }
    __shared__ float red[8];
#pragma unroll
    for (int o = 16; o > 0; o >>= 1) mx = fmaxf(mx, __shfl_xor_sync(0xffffffffu, mx, o));
    if ((threadIdx.x & 31) == 0) red[threadIdx.x >> 5] = mx;
    __syncthreads();
    if (threadIdx.x == 0) {
        float m = red[0];
#pragma unroll
        for (int wN = 1; wN < 8; wN++) m = fmaxf(m, red[wN]);
        red[0] = fmaxf(m, 1e-6f);
    }
    __syncthreads();
    float inv = 1.f / red[0];
    const float* imr = im + (size_t)bq * NSEQ;
    float* br = g_bias + (size_t)bq * NSEQ;
    for (int k = threadIdx.x; k < NSEQ; k += 256) {
        float s = c0 * cmb[k] + c1 * cmb[NSEQ + k] + c2 * cmb[2 * NSEQ + k] + c3 * cmb[3 * NSEQ + k];
        br[k] = 2.f * s * inv - 1.f + 0.3f * imr[k];
    }
}

// ---------------- HMMA flash attention ----------------
// grid (NSEQ/128, BH), 256 threads / 8 warps; warp owns 16 q-rows x 64 keys.
// Epilogue writes O directly as bf16 hi/lo swizzled A-tiles for the out-projection.
#define ATTN2_SMEM 98304

__global__ void __launch_bounds__(256)
attn2_kernel(const float* __restrict__ gate)
{
    extern __shared__ char smraw[];
    const uint32_t S = smem_u32(smraw);
    const int tid = threadIdx.x, lane = tid & 31, warp = tid >> 5;
    const int bh = blockIdx.y, b = bh >> 4, h = bh & 15;
    const int qt = blockIdx.x, q0 = qt * 128;
    const float g3 = 3.f * fminf(fmaxf(gate[h], 0.f), 1.f);
    const int lrow = lane & 15, cb = (lane >> 4) << 4;
    const int wrow = warp * 16;

    {
        size_t qoff = ((size_t)(bh * 16 + qt)) * 16384 + tid * 16;
        uint32_t d = S + tid * 16;
#pragma unroll
        for (int i = 0; i < 4; i++) {
            CP_ASYNC16(d + i * 4096,         (const char*)gQh + qoff + i * 4096);
            CP_ASYNC16(d + 16384 + i * 4096, (const char*)gQl + qoff + i * 4096);
        }
        CP_COMMIT();
    }
    {
        size_t koff = ((size_t)(bh * 16)) * 16384 + tid * 16;
        size_t voff = ((size_t)(bh * 32)) * 8192 + tid * 16;
        uint32_t d = S + 32768 + tid * 16;
#pragma unroll
        for (int i = 0; i < 2; i++) {
            CP_ASYNC16(d + 0     + i * 4096, (const char*)gKh  + koff + i * 4096);
            CP_ASYNC16(d + 8192  + i * 4096, (const char*)gKl  + koff + i * 4096);
            CP_ASYNC16(d + 16384 + i * 4096, (const char*)gVth + voff + i * 4096);
            CP_ASYNC16(d + 24576 + i * 4096, (const char*)gVtl + voff + i * 4096);
        }
        CP_COMMIT();
    }

    uint32_t qh[4][4], ql[4][4];
    float o[8][4];
#pragma unroll
    for (int nf = 0; nf < 8; nf++)
#pragma unroll
        for (int t = 0; t < 4; t++) o[nf][t] = 0.f;
    float m0r = -1e30f, m1r = -1e30f, l0r = 0.f, l1r = 0.f;

    const int r0l = lane >> 2;
    const float* bias0 = g_bias + ((size_t)(b * NSEQ + q0 + wrow + r0l)) * NSEQ;
    const float* bias1 = bias0 + 8 * NSEQ;

    for (int kt = 0; kt < 32; kt++) {
        __syncthreads();
        if (kt + 1 < 32) {
            int k2 = kt + 1;
            size_t koff = ((size_t)(bh * 16 + (k2 >> 1))) * 16384 + (size_t)(k2 & 1) * 8192 + tid * 16;
            size_t voff = ((size_t)(bh * 32 + k2)) * 8192 + tid * 16;
            uint32_t d = S + 32768 + (k2 & 1) * 32768 + tid * 16;
#pragma unroll
            for (int i = 0; i < 2; i++) {
                CP_ASYNC16(d + 0     + i * 4096, (const char*)gKh  + koff + i * 4096);
                CP_ASYNC16(d + 8192  + i * 4096, (const char*)gKl  + koff + i * 4096);
                CP_ASYNC16(d + 16384 + i * 4096, (const char*)gVth + voff + i * 4096);
                CP_ASYNC16(d + 24576 + i * 4096, (const char*)gVtl + voff + i * 4096);
            }
            CP_COMMIT();
            CP_WAIT1();
        } else {
            CP_WAIT0();
        }
        __syncthreads();

        if (kt == 0) {
#pragma unroll
            for (int ks = 0; ks < 4; ks++) {
                uint32_t off = (wrow + lrow) * 128 + ks * 32 + cb;
                uint32_t sw = off ^ (((wrow + lrow) & 7) << 4);
                LDMX4(qh[ks], S + sw);
                LDMX4(ql[ks], S + 16384 + sw);
            }
        }

        uint32_t buf = S + 32768 + (kt & 1) * 32768;

        float sf[8][4];
#pragma unroll
        for (int nf = 0; nf < 8; nf++)
#pragma unroll
            for (int t = 0; t < 4; t++) sf[nf][t] = 0.f;

#pragma unroll
        for (int ks = 0; ks < 4; ks++) {
#pragma unroll
            for (int nf2 = 0; nf2 < 4; nf2++) {
                uint32_t off = (nf2 * 16 + lrow) * 128 + ks * 32 + cb;
                uint32_t sw = off ^ ((lrow & 7) << 4);
                uint32_t kh_[4], kl_[4];
                LDMX4(kh_, buf + sw);
                LDMX4(kl_, buf + 8192 + sw);
                float* d0 = sf[2 * nf2];
                float* d1 = sf[2 * nf2 + 1];
                mma_bf16(d0, qh[ks][0], qh[ks][1], qh[ks][2], qh[ks][3], kh_[0], kh_[2]);
                mma_bf16(d0, qh[ks][0], qh[ks][1], qh[ks][2], qh[ks][3], kl_[0], kl_[2]);
                mma_bf16(d0, ql[ks][0], ql[ks][1], ql[ks][2], ql[ks][3], kh_[0], kh_[2]);
                mma_bf16(d1, qh[ks][0], qh[ks][1], qh[ks][2], qh[ks][3], kh_[1], kh_[3]);
                mma_bf16(d1, qh[ks][0], qh[ks][1], qh[ks][2], qh[ks][3], kl_[1], kl_[3]);
                mma_bf16(d1, ql[ks][0], ql[ks][1], ql[ks][2], ql[ks][3], kh_[1], kh_[3]);
            }
        }

        int colbase = kt * 64 + 2 * (lane & 3);
        float rm0 = -1e30f, rm1 = -1e30f;
#pragma unroll
        for (int nf = 0; nf < 8; nf++) {
            float2 bb0 = *(const float2*)(bias0 + colbase + nf * 8);
            float2 bb1 = *(const float2*)(bias1 + colbase + nf * 8);
            sf[nf][0] = fmaf(sf[nf][0], 0.125f, g3 * bb0.x);
            sf[nf][1] = fmaf(sf[nf][1], 0.125f, g3 * bb0.y);
            sf[nf][2] = fmaf(sf[nf][2], 0.125f, g3 * bb1.x);
            sf[nf][3] = fmaf(sf[nf][3], 0.125f, g3 * bb1.y);
            rm0 = fmaxf(rm0, fmaxf(sf[nf][0], sf[nf][1]));
            rm1 = fmaxf(rm1, fmaxf(sf[nf][2], sf[nf][3]));
        }
        rm0 = fmaxf(rm0, __shfl_xor_sync(0xffffffffu, rm0, 1));
        rm0 = fmaxf(rm0, __shfl_xor_sync(0xffffffffu, rm0, 2));
        rm1 = fmaxf(rm1, __shfl_xor_sync(0xffffffffu, rm1, 1));
        rm1 = fmaxf(rm1, __shfl_xor_sync(0xffffffffu, rm1, 2));

        float mn0 = fmaxf(m0r, rm0), mn1 = fmaxf(m1r, rm1);
        float al0 = __expf(m0r - mn0), al1 = __expf(m1r - mn1);
        m0r = mn0; m1r = mn1;
        float rs0 = 0.f, rs1 = 0.f;
#pragma unroll
        for (int nf = 0; nf < 8; nf++) {
            sf[nf][0] = __expf(sf[nf][0] - mn0);
            sf[nf][1] = __expf(sf[nf][1] - mn0);
            sf[nf][2] = __expf(sf[nf][2] - mn1);
            sf[nf][3] = __expf(sf[nf][3] - mn1);
            rs0 += sf[nf][0] + sf[nf][1];
            rs1 += sf[nf][2] + sf[nf][3];
        }
        rs0 += __shfl_xor_sync(0xffffffffu, rs0, 1);
        rs0 += __shfl_xor_sync(0xffffffffu, rs0, 2);
        rs1 += __shfl_xor_sync(0xffffffffu, rs1, 1);
        rs1 += __shfl_xor_sync(0xffffffffu, rs1, 2);
        l0r = l0r * al0 + rs0;
        l1r = l1r * al1 + rs1;
#pragma unroll
        for (int nf = 0; nf < 8; nf++) {
            o[nf][0] *= al0; o[nf][1] *= al0;
            o[nf][2] *= al1; o[nf][3] *= al1;
        }

#pragma unroll
        for (int kk = 0; kk < 4; kk++) {
            const int na = 2 * kk, nb = 2 * kk + 1;
            uint32_t u0 = __float_as_uint(sf[na][0]), u1 = __float_as_uint(sf[na][1]);
            uint32_t u2 = __float_as_uint(sf[na][2]), u3 = __float_as_uint(sf[na][3]);
            uint32_t w0 = __float_as_uint(sf[nb][0]), w1 = __float_as_uint(sf[nb][1]);
            uint32_t w2 = __float_as_uint(sf[nb][2]), w3 = __float_as_uint(sf[nb][3]);
            uint32_t ph_[4], pl_[4];
            ph_[0] = pack2_hi(u0, u1);
            ph_[1] = pack2_hi(u2, u3);
            ph_[2] = pack2_hi(w0, w1);
            ph_[3] = pack2_hi(w2, w3);
            pl_[0] = pack2_bf16(sf[na][0] - __uint_as_float(u0 & 0xFFFF0000u),
                                sf[na][1] - __uint_as_float(u1 & 0xFFFF0000u));
            pl_[1] = pack2_bf16(sf[na][2] - __uint_as_float(u2 & 0xFFFF0000u),
                                sf[na][3] - __uint_as_float(u3 & 0xFFFF0000u));
            pl_[2] = pack2_bf16(sf[nb][0] - __uint_as_float(w0 & 0xFFFF0000u),
                                sf[nb][1] - __uint_as_float(w1 & 0xFFFF0000u));
            pl_[3] = pack2_bf16(sf[nb][2] - __uint_as_float(w2 & 0xFFFF0000u),
                                sf[nb][3] - __uint_as_float(w3 & 0xFFFF0000u));
#pragma unroll
            for (int nf2 = 0; nf2 < 4; nf2++) {
                uint32_t off = (nf2 * 16 + lrow) * 128 + kk * 32 + cb;
                uint32_t sw = off ^ ((lrow & 7) << 4);
                uint32_t vh_[4], vl_[4];
                LDMX4(vh_, buf + 16384 + sw);
                LDMX4(vl_, buf + 24576 + sw);
                float* d0 = o[2 * nf2];
                float* d1 = o[2 * nf2 + 1];
                mma_bf16(d0, ph_[0], ph_[1], ph_[2], ph_[3], vh_[0], vh_[2]);
                mma_bf16(d0, ph_[0], ph_[1], ph_[2], ph_[3], vl_[0], vl_[2]);
                mma_bf16(d0, pl_[0], pl_[1], pl_[2], pl_[3], vh_[0], vh_[2]);
                mma_bf16(d1, ph_[0], ph_[1], ph_[2], ph_[3], vh_[1], vh_[3]);
                mma_bf16(d1, ph_[0], ph_[1], ph_[2], ph_[3], vl_[1], vl_[3]);
                mma_bf16(d1, pl_[0], pl_[1], pl_[2], pl_[3], vh_[1], vh_[3]);
            }
        }
    }

    // epilogue: normalize + write bf16 hi/lo swizzled A-tile for the out-projection
    float i0 = 1.f / l0r, i1 = 1.f / l1r;
    size_t tb = (((size_t)(b * 16 + qt)) * 16 + h) * 16384;
    int lr0 = wrow + r0l, lr1 = lr0 + 8;
    uint32_t x0 = (lr0 & 7) << 4, x1 = (lr1 & 7) << 4;
#pragma unroll
    for (int nf = 0; nf < 8; nf++) {
        int dd = nf * 8 + 2 * (lane & 3);
        float v0 = o[nf][0] * i0, v1 = o[nf][1] * i0;
        float v2 = o[nf][2] * i1, v3 = o[nf][3] * i1;
        uint32_t u0 = __float_as_uint(v0), u1 = __float_as_uint(v1);
        uint32_t u2 = __float_as_uint(v2), u3 = __float_as_uint(v3);
        uint32_t o0 = (lr0 * 128 + dd * 2) ^ x0;
        uint32_t o1 = (lr1 * 128 + dd * 2) ^ x1;
        *(uint32_t*)((char*)gAh2 + tb + o0) = pack2_hi(u0, u1);
        *(uint32_t*)((char*)gAh2 + tb + o1) = pack2_hi(u2, u3);
        *(uint32_t*)((char*)gAl2 + tb + o0) =
            pack2_bf16(v0 - __uint_as_float(u0 & 0xFFFF0000u),
                       v1 - __uint_as_float(u1 & 0xFFFF0000u));
        *(uint32_t*)((char*)gAl2 + tb + o1) =
            pack2_bf16(v2 - __uint_as_float(u2 & 0xFFFF0000u),
                       v3 - __uint_as_float(u3 & 0xFFFF0000u));
    }
}

// ---------------- launch ----------------
extern "C" void kernel_launch(void* const* d_in, const int* in_sizes, int n_in,
                              void* d_out, int out_size)
{
    (void)in_sizes; (void)n_in; (void)out_size;
    const float* x    = (const float*)d_in[0];
    const float* cm   = (const float*)d_in[1];
    const float* im   = (const float*)d_in[2];
    const float* wqkv = (const float*)d_in[3];
    const float* wout = (const float*)d_in[4];
    const float* qnw  = (const float*)d_in[5];
    const float* knw  = (const float*)d_in[6];
    const float* gate = (const float*)d_in[7];
    float* out = (float*)d_out;

    void *xh, *xl, *wqh, *wql, *woh, *wol, *ah2, *al2;
    cudaGetSymbolAddress(&xh, gXh);   cudaGetSymbolAddress(&xl, gXl);
    cudaGetSymbolAddress(&wqh, gWqh); cudaGetSymbolAddress(&wql, gWql);
    cudaGetSymbolAddress(&woh, gWoh); cudaGetSymbolAddress(&wol, gWol);
    cudaGetSymbolAddress(&ah2, gAh2); cudaGetSymbolAddress(&al2, gAl2);

    cudaFuncSetAttribute(attn2_kernel, cudaFuncAttributeMaxDynamicSharedMemorySize, ATTN2_SMEM);
    cudaFuncSetAttribute(gemm_hmma<0>, cudaFuncAttributeMaxDynamicSharedMemorySize, GEMM_SMEM);
    cudaFuncSetAttribute(gemm_hmma<1>, cudaFuncAttributeMaxDynamicSharedMemorySize, GEMM_SMEM);

    const int M = BB * NSEQ;   // 4096

    // 1) split-convert inputs
    conv_split_kernel<<<(4096 * 1024 / 8) / 256, 256>>>(x,    (__nv_bfloat16*)xh,  (__nv_bfloat16*)xl,  1024);
    conv_split_kernel<<<(3072 * 1024 / 8) / 256, 256>>>(wqkv, (__nv_bfloat16*)wqh, (__nv_bfloat16*)wql, 1024);
    conv_split_kernel<<<(1024 * 1024 / 8) / 256, 256>>>(wout, (__nv_bfloat16*)woh, (__nv_bfloat16*)wol, 1024);

    // 2) QKV projection (HMMA) with fused RMSNorm + split epilogue
    gemm_hmma<1><<<dim3(3 * DMOD / 128, M / 128), 512, GEMM_SMEM>>>(
        (const char*)xh, (const char*)xl, (const char*)wqh, (const char*)wql,
        nullptr, 1024 / 64, 3 * DMOD, qnw, knw);

    // 3) V -> transposed bf16 hi/lo tiles
    vsplit_kernel<<<dim3(NSEQ / 64, BH), 256>>>();

    // 4) bias precompute
    bias_kernel<<<BB * NSEQ, 256>>>(cm, im);

    // 5) HMMA flash attention (writes split A-tiles for out-proj directly)
    attn2_kernel<<<dim3(NSEQ / 128, BH), 256, ATTN2_SMEM>>>(gate);

    // 6) out-projection straight into d_out
    gemm_hmma<0><<<dim3(DMOD / 128, M / 128), 512, GEMM_SMEM>>>(
        (const char*)ah2, (const char*)al2, (const char*)woh, (const char*)wol,
        out, 1024 / 64, DMOD, nullptr, nullptr);
}